// round 2
// baseline (speedup 1.0000x reference)
#include <cuda_runtime.h>
#include <cuda_bf16.h>
#include <math.h>

// ---------------- problem constants ----------------
#define S_LEN   2048
#define D_MODEL 1024
#define H_HEADS 32
#define P_DIM   64
#define N_STATE 64
#define G_GRP   8
#define K_CONV  4
#define D_INNER 2048                 // H*P
#define CONV_DIM 3072                // D_INNER + 2*G*N
#define D_PROJ  5152                 // 2*D_INNER + 2*G*N + H
#define GROUP_SIZE 256               // D_INNER / G
#define EPS_RMS 1e-5f

// proj row offsets
#define OFF_Z    0
#define OFF_XBC  2048
#define OFF_DT   5120
// xbc row offsets
#define OFF_XS   0
#define OFF_B    2048
#define OFF_C    2560

// ---------------- scratch (device globals; no allocation allowed) ----------------
__device__ __align__(16) float g_xn  [S_LEN * D_MODEL];
__device__ __align__(16) float g_proj[S_LEN * D_PROJ];
__device__ __align__(16) float g_xbc [S_LEN * CONV_DIM];
__device__ __align__(16) float g_dt  [S_LEN * H_HEADS];
__device__ __align__(16) float g_dA  [S_LEN * H_HEADS];
__device__ __align__(16) float g_y   [S_LEN * D_INNER];
__device__ __align__(16) float g_g   [S_LEN * D_INNER];

__device__ __forceinline__ float sigmoidf_(float x) { return 1.0f / (1.0f + expf(-x)); }
__device__ __forceinline__ float siluf_(float x)    { return x * sigmoidf_(x); }

// ---------------- 1. RMSNorm ----------------
__global__ void rmsnorm_kernel(const float* __restrict__ x,
                               const float* __restrict__ w)
{
    int s = blockIdx.x;
    int tid = threadIdx.x;                   // 256
    const float* row = x + (size_t)s * D_MODEL;
    float v[4];
    float ss = 0.f;
#pragma unroll
    for (int i = 0; i < 4; i++) {
        v[i] = row[tid + i * 256];
        ss += v[i] * v[i];
    }
    __shared__ float red[8];
#pragma unroll
    for (int o = 16; o > 0; o >>= 1) ss += __shfl_xor_sync(0xffffffffu, ss, o);
    if ((tid & 31) == 0) red[tid >> 5] = ss;
    __syncthreads();
    __shared__ float rinv;
    if (tid == 0) {
        float t = 0.f;
#pragma unroll
        for (int i = 0; i < 8; i++) t += red[i];
        rinv = rsqrtf(t / (float)D_MODEL + EPS_RMS);
    }
    __syncthreads();
    float r = rinv;
    float* o = g_xn + (size_t)s * D_MODEL;
#pragma unroll
    for (int i = 0; i < 4; i++) {
        int c = tid + i * 256;
        o[c] = v[i] * r * w[c];
    }
}

// ---------------- 2. fp32 tiled GEMM: C[M,N] = A[M,K] @ B[K,N] (+resid) ----------------
// BM=128, BN=64, BK=16, 256 threads, per-thread 8x4, float4 staged loads.
// Requires: M % 128 == 0, K % 16 == 0, N % 4 == 0, A/B 16B-aligned.
__global__ void gemm_kernel(const float* __restrict__ A,
                            const float* __restrict__ B,
                            const float* __restrict__ resid,  // may be null
                            float* __restrict__ C,
                            int M, int N, int K)
{
    __shared__ float As[128][16];
    __shared__ float Bs[16][64];

    int tid = threadIdx.x;
    int tx = tid & 15;           // 0..15 -> col group
    int ty = tid >> 4;           // 0..15 -> row group
    int rowBase = blockIdx.y * 128;
    int colBase = blockIdx.x * 64;

    float acc[8][4];
#pragma unroll
    for (int i = 0; i < 8; i++)
#pragma unroll
        for (int j = 0; j < 4; j++) acc[i][j] = 0.f;

    for (int k0 = 0; k0 < K; k0 += 16) {
        // A tile: 128x16 = 512 float4; 2 per thread
#pragma unroll
        for (int i = 0; i < 2; i++) {
            int idx = tid * 2 + i;          // 0..511
            int r   = idx >> 2;             // 0..127
            int kq  = idx & 3;              // float4 index within row
            float4 v = *reinterpret_cast<const float4*>(
                A + (size_t)(rowBase + r) * K + k0 + kq * 4);
            As[r][kq * 4 + 0] = v.x;
            As[r][kq * 4 + 1] = v.y;
            As[r][kq * 4 + 2] = v.z;
            As[r][kq * 4 + 3] = v.w;
        }
        // B tile: 16x64 = 256 float4; 1 per thread
        {
            int kk = tid >> 4;              // 0..15
            int cq = tid & 15;              // 0..15
            int gc = colBase + cq * 4;
            float4 v;
            if (gc + 3 < N) {
                v = *reinterpret_cast<const float4*>(
                    B + (size_t)(k0 + kk) * N + gc);
            } else {
                v = make_float4(0.f, 0.f, 0.f, 0.f);
            }
            Bs[kk][cq * 4 + 0] = v.x;
            Bs[kk][cq * 4 + 1] = v.y;
            Bs[kk][cq * 4 + 2] = v.z;
            Bs[kk][cq * 4 + 3] = v.w;
        }
        __syncthreads();
#pragma unroll
        for (int kk = 0; kk < 16; kk++) {
            float a[8], b[4];
#pragma unroll
            for (int i = 0; i < 8; i++) a[i] = As[ty * 8 + i][kk];
#pragma unroll
            for (int j = 0; j < 4; j++) b[j] = Bs[kk][tx * 4 + j];
#pragma unroll
            for (int i = 0; i < 8; i++)
#pragma unroll
                for (int j = 0; j < 4; j++) acc[i][j] += a[i] * b[j];
        }
        __syncthreads();
    }

#pragma unroll
    for (int i = 0; i < 8; i++) {
        int gr = rowBase + ty * 8 + i;
#pragma unroll
        for (int j = 0; j < 4; j++) {
            int gc = colBase + tx * 4 + j;
            if (gc < N) {
                float v = acc[i][j];
                if (resid) v += resid[(size_t)gr * N + gc];
                C[(size_t)gr * N + gc] = v;
            }
        }
    }
}

// ---------------- 3. causal depthwise conv (K=4) + bias + SiLU ----------------
__global__ void conv_silu_kernel(const float* __restrict__ cw,
                                 const float* __restrict__ cb)
{
    int c = blockIdx.x * 256 + threadIdx.x;   // 0..3071
    int s = blockIdx.y;
    float acc = cb[c];
#pragma unroll
    for (int k = 0; k < K_CONV; k++) {
        int ss = s - (K_CONV - 1) + k;
        if (ss >= 0)
            acc += cw[c * K_CONV + k] * g_proj[(size_t)ss * D_PROJ + OFF_XBC + c];
    }
    g_xbc[(size_t)s * CONV_DIM + c] = siluf_(acc);
}

// ---------------- 4. dt / dA ----------------
__global__ void dt_kernel(const float* __restrict__ dt_bias,
                          const float* __restrict__ A_log)
{
    int idx = blockIdx.x * 256 + threadIdx.x;   // S*H
    int s = idx >> 5;
    int h = idx & 31;
    float x = g_proj[(size_t)s * D_PROJ + OFF_DT + h] + dt_bias[h];
    float dt = (x > 20.f) ? x : log1pf(expf(x));
    float A = -expf(A_log[h]);
    g_dt[idx] = dt;
    g_dA[idx] = expf(dt * A);
}

// ---------------- 5. sequential SSM scan ----------------
// grid = H (32 blocks), block = 256 threads.
// warp w covers p in [w*8, w*8+8); lane layout: p = w*8 + (lane&7), quarter = lane>>3
// thread owns n in [quarter*16, quarter*16+16): 16 state registers.
#define CHUNK 16
__global__ void scan_kernel()
{
    int h = blockIdx.x;
    int g = h >> 2;                 // group = h / (H/G) = h/4
    int tid = threadIdx.x;
    int w = tid >> 5;
    int lane = tid & 31;
    int p = w * 8 + (lane & 7);
    int quarter = lane >> 3;
    int nbase = quarter * 16;

    __shared__ float sx[CHUNK][64];
    __shared__ float sB[CHUNK][64];
    __shared__ float sC[CHUNK][64];
    __shared__ float sdA[CHUNK];
    __shared__ float sdt[CHUNK];
    __shared__ float sy[CHUNK][64];

    float hs[16];
#pragma unroll
    for (int i = 0; i < 16; i++) hs[i] = 0.f;

    for (int s0 = 0; s0 < S_LEN; s0 += CHUNK) {
        // stage chunk inputs
#pragma unroll
        for (int i = 0; i < 4; i++) {
            int t  = tid + i * 256;
            int tt = t >> 6;
            int cc = t & 63;
            size_t base = (size_t)(s0 + tt) * CONV_DIM;
            sx[tt][cc] = g_xbc[base + OFF_XS + h * 64 + cc];
            sB[tt][cc] = g_xbc[base + OFF_B  + g * 64 + cc];
            sC[tt][cc] = g_xbc[base + OFF_C  + g * 64 + cc];
        }
        if (tid < CHUNK) {
            sdA[tid] = g_dA[(size_t)(s0 + tid) * H_HEADS + h];
            sdt[tid] = g_dt[(size_t)(s0 + tid) * H_HEADS + h];
        }
        __syncthreads();

#pragma unroll 4
        for (int t = 0; t < CHUNK; t++) {
            float dAv  = sdA[t];
            float coef = sdt[t] * sx[t][p];
            float y = 0.f;
#pragma unroll
            for (int i = 0; i < 16; i++) {
                float b  = sB[t][nbase + i];
                float cv = sC[t][nbase + i];
                hs[i] = dAv * hs[i] + coef * b;
                y += hs[i] * cv;
            }
            y += __shfl_xor_sync(0xffffffffu, y, 8);
            y += __shfl_xor_sync(0xffffffffu, y, 16);
            if (quarter == 0) sy[t][p] = y;
        }
        __syncthreads();

        // coalesced writeback of y chunk
#pragma unroll
        for (int i = 0; i < 4; i++) {
            int t  = tid + i * 256;
            int tt = t >> 6;
            int cc = t & 63;
            g_y[(size_t)(s0 + tt) * D_INNER + h * 64 + cc] = sy[tt][cc];
        }
        __syncthreads();
    }
}

// ---------------- 6. gating + grouped RMSNorm ----------------
// grid (G, S), block 256 (= GROUP_SIZE)
__global__ void gate_kernel(const float* __restrict__ Dv,
                            const float* __restrict__ gw)
{
    int s = blockIdx.y;
    int grp = blockIdx.x;
    int tid = threadIdx.x;
    int d = grp * GROUP_SIZE + tid;
    int h = d >> 6;

    float xs = g_xbc[(size_t)s * CONV_DIM + OFF_XS + d];
    float y  = g_y[(size_t)s * D_INNER + d] + Dv[h] * xs;
    float z  = g_proj[(size_t)s * D_PROJ + OFF_Z + d];
    float gv = y * siluf_(z);

    float ss = gv * gv;
    __shared__ float red[8];
#pragma unroll
    for (int o = 16; o > 0; o >>= 1) ss += __shfl_xor_sync(0xffffffffu, ss, o);
    if ((tid & 31) == 0) red[tid >> 5] = ss;
    __syncthreads();
    __shared__ float rinv;
    if (tid == 0) {
        float t = 0.f;
#pragma unroll
        for (int i = 0; i < 8; i++) t += red[i];
        rinv = rsqrtf(t / (float)GROUP_SIZE + EPS_RMS);
    }
    __syncthreads();
    g_g[(size_t)s * D_INNER + d] = gv * rinv * gw[d];
}

// ---------------- launch ----------------
extern "C" void kernel_launch(void* const* d_in, const int* in_sizes, int n_in,
                              void* d_out, int out_size)
{
    const float* hidden      = (const float*)d_in[0];
    const float* norm_w      = (const float*)d_in[1];
    const float* in_proj_w   = (const float*)d_in[2];
    const float* conv_w      = (const float*)d_in[3];
    const float* conv_b      = (const float*)d_in[4];
    const float* dt_bias     = (const float*)d_in[5];
    const float* A_log       = (const float*)d_in[6];
    const float* Dv          = (const float*)d_in[7];
    const float* gate_norm_w = (const float*)d_in[8];
    const float* out_proj_w  = (const float*)d_in[9];
    float* out = (float*)d_out;

    // resolve scratch symbol addresses (host-side query, capture-safe, no allocation)
    void *p_xn, *p_proj, *p_g;
    cudaGetSymbolAddress(&p_xn,   g_xn);
    cudaGetSymbolAddress(&p_proj, g_proj);
    cudaGetSymbolAddress(&p_g,    g_g);

    rmsnorm_kernel<<<S_LEN, 256>>>(hidden, norm_w);

    gemm_kernel<<<dim3((D_PROJ + 63) / 64, S_LEN / 128), 256>>>(
        (const float*)p_xn, in_proj_w, nullptr, (float*)p_proj,
        S_LEN, D_PROJ, D_MODEL);

    conv_silu_kernel<<<dim3(CONV_DIM / 256, S_LEN), 256>>>(conv_w, conv_b);

    dt_kernel<<<(S_LEN * H_HEADS) / 256, 256>>>(dt_bias, A_log);

    scan_kernel<<<H_HEADS, 256>>>();

    gate_kernel<<<dim3(G_GRP, S_LEN), 256>>>(Dv, gate_norm_w);

    gemm_kernel<<<dim3(D_MODEL / 64, S_LEN / 128), 256>>>(
        (const float*)p_g, out_proj_w, hidden, out,
        S_LEN, D_MODEL, D_INNER);
}

// round 3
// speedup vs baseline: 1.5552x; 1.5552x over previous
#include <cuda_runtime.h>
#include <cuda_bf16.h>
#include <math.h>
#include <stdint.h>

// ---------------- problem constants ----------------
#define S_LEN   2048
#define D_MODEL 1024
#define H_HEADS 32
#define P_DIM   64
#define N_STATE 64
#define G_GRP   8
#define K_CONV  4
#define D_INNER 2048                 // H*P
#define CONV_DIM 3072                // D_INNER + 2*G*N
#define D_PROJ  5152                 // 2*D_INNER + 2*G*N + H
#define GROUP_SIZE 256               // D_INNER / G
#define EPS_RMS 1e-5f

// proj row offsets
#define OFF_Z    0
#define OFF_XBC  2048
#define OFF_DT   5120
// xbc row offsets
#define OFF_XS   0
#define OFF_B    2048
#define OFF_C    2560

// ---------------- scratch (device globals; no allocation allowed) ----------------
__device__ __align__(16) float g_xn  [S_LEN * D_MODEL];
__device__ __align__(16) float g_proj[S_LEN * D_PROJ];
__device__ __align__(16) float g_xbc [S_LEN * CONV_DIM];
__device__ __align__(16) float g_dt  [S_LEN * H_HEADS];
__device__ __align__(16) float g_dA  [S_LEN * H_HEADS];
__device__ __align__(16) float g_y   [S_LEN * D_INNER];
__device__ __align__(16) float g_g   [S_LEN * D_INNER];

__device__ __forceinline__ float sigmoidf_(float x) { return 1.0f / (1.0f + expf(-x)); }
__device__ __forceinline__ float siluf_(float x)    { return x * sigmoidf_(x); }

__device__ __forceinline__ uint32_t f2tf32(float f) {
    uint32_t u;
    asm("cvt.rna.tf32.f32 %0, %1;" : "=r"(u) : "f"(f));
    return u;
}

__device__ __forceinline__ void mma_tf32(float* c, const uint32_t* a,
                                         uint32_t b0, uint32_t b1) {
    asm volatile(
        "mma.sync.aligned.m16n8k8.row.col.f32.tf32.tf32.f32 "
        "{%0,%1,%2,%3}, {%4,%5,%6,%7}, {%8,%9}, {%0,%1,%2,%3};"
        : "+f"(c[0]), "+f"(c[1]), "+f"(c[2]), "+f"(c[3])
        : "r"(a[0]), "r"(a[1]), "r"(a[2]), "r"(a[3]), "r"(b0), "r"(b1));
}

// ---------------- 1. RMSNorm ----------------
__global__ void rmsnorm_kernel(const float* __restrict__ x,
                               const float* __restrict__ w)
{
    int s = blockIdx.x;
    int tid = threadIdx.x;                   // 256
    const float* row = x + (size_t)s * D_MODEL;
    float v[4];
    float ss = 0.f;
#pragma unroll
    for (int i = 0; i < 4; i++) {
        v[i] = row[tid + i * 256];
        ss += v[i] * v[i];
    }
    __shared__ float red[8];
#pragma unroll
    for (int o = 16; o > 0; o >>= 1) ss += __shfl_xor_sync(0xffffffffu, ss, o);
    if ((tid & 31) == 0) red[tid >> 5] = ss;
    __syncthreads();
    __shared__ float rinv;
    if (tid == 0) {
        float t = 0.f;
#pragma unroll
        for (int i = 0; i < 8; i++) t += red[i];
        rinv = rsqrtf(t / (float)D_MODEL + EPS_RMS);
    }
    __syncthreads();
    float r = rinv;
    float* o = g_xn + (size_t)s * D_MODEL;
#pragma unroll
    for (int i = 0; i < 4; i++) {
        int c = tid + i * 256;
        o[c] = v[i] * r * w[c];
    }
}

// ---------------- 2. tf32 tensor-core GEMM: C[M,N] = A[M,K] @ B[K,N] (+resid) ----
// BM=128, BN=128, BK=16, 256 threads (8 warps: 4 warpM x 2 warpN, warp tile 32x64)
// Requires: M % 128 == 0, K % 16 == 0, N % 4 == 0, A/B 16B-aligned.
#define GBM 128
#define GBN 128
#define GBK 16
#define GPAD 136   // row stride (floats); mod 32 == 8 -> conflict-free frag LDS

__global__ __launch_bounds__(256, 1)
void gemm_tf32_kernel(const float* __restrict__ A,
                      const float* __restrict__ B,
                      const float* __restrict__ resid,  // may be null
                      float* __restrict__ C,
                      int M, int N, int K)
{
    __shared__ uint32_t As[2][GBK][GPAD];   // [k][m]
    __shared__ uint32_t Bs[2][GBK][GPAD];   // [k][n]

    int tid = threadIdx.x;
    int wid = tid >> 5, lane = tid & 31;
    int warpM = wid & 3;        // m base = warpM*32
    int warpN = wid >> 2;       // n base = warpN*64
    int grp = lane >> 2, tig = lane & 3;

    int rowBase = blockIdx.y * GBM;
    int colBase = blockIdx.x * GBN;

    float acc[2][8][4];
#pragma unroll
    for (int mt = 0; mt < 2; mt++)
#pragma unroll
        for (int nt = 0; nt < 8; nt++)
#pragma unroll
            for (int r = 0; r < 4; r++) acc[mt][nt][r] = 0.f;

    int KT = K / GBK;

    // ---- stage loader ----
    auto load_stage = [&](int kt, int buf) {
        int k0 = kt * GBK;
        // A tile: 128 rows x 16 k = 512 float4 (4 per row); transpose to [k][m]
#pragma unroll
        for (int i = 0; i < 2; i++) {
            int idx = tid + i * 256;        // 0..511
            int r  = idx >> 2;              // 0..127
            int kq = idx & 3;
            float4 v = *reinterpret_cast<const float4*>(
                A + (size_t)(rowBase + r) * K + k0 + kq * 4);
            As[buf][kq * 4 + 0][r] = f2tf32(v.x);
            As[buf][kq * 4 + 1][r] = f2tf32(v.y);
            As[buf][kq * 4 + 2][r] = f2tf32(v.z);
            As[buf][kq * 4 + 3][r] = f2tf32(v.w);
        }
        // B tile: 16 rows x 128 cols = 512 float4 (32 per row)
#pragma unroll
        for (int i = 0; i < 2; i++) {
            int idx = tid + i * 256;
            int kk = idx >> 5;              // 0..15
            int cq = idx & 31;              // 0..31
            int gc = colBase + cq * 4;
            float4 v = make_float4(0.f, 0.f, 0.f, 0.f);
            if (gc < N) {  // N % 4 == 0 and gc % 4 == 0 -> all-or-nothing
                v = *reinterpret_cast<const float4*>(
                    B + (size_t)(k0 + kk) * N + gc);
            }
            uint4 u;
            u.x = f2tf32(v.x); u.y = f2tf32(v.y);
            u.z = f2tf32(v.z); u.w = f2tf32(v.w);
            *reinterpret_cast<uint4*>(&Bs[buf][kk][cq * 4]) = u;
        }
    };

    load_stage(0, 0);

    for (int kt = 0; kt < KT; kt++) {
        __syncthreads();
        if (kt + 1 < KT) load_stage(kt + 1, (kt + 1) & 1);
        int buf = kt & 1;
#pragma unroll
        for (int k8 = 0; k8 < 2; k8++) {
            int kb = k8 * 8;
            uint32_t a[2][4];
#pragma unroll
            for (int mt = 0; mt < 2; mt++) {
                int m = warpM * 32 + mt * 16;
                a[mt][0] = As[buf][kb + tig    ][m + grp];
                a[mt][1] = As[buf][kb + tig    ][m + grp + 8];
                a[mt][2] = As[buf][kb + tig + 4][m + grp];
                a[mt][3] = As[buf][kb + tig + 4][m + grp + 8];
            }
#pragma unroll
            for (int nt = 0; nt < 8; nt++) {
                int n = warpN * 64 + nt * 8;
                uint32_t b0 = Bs[buf][kb + tig    ][n + grp];
                uint32_t b1 = Bs[buf][kb + tig + 4][n + grp];
                mma_tf32(acc[0][nt], a[0], b0, b1);
                mma_tf32(acc[1][nt], a[1], b0, b1);
            }
        }
    }

    // ---- epilogue ----
#pragma unroll
    for (int mt = 0; mt < 2; mt++) {
        int row0 = rowBase + warpM * 32 + mt * 16 + grp;
#pragma unroll
        for (int nt = 0; nt < 8; nt++) {
            int col0 = colBase + warpN * 64 + nt * 8 + tig * 2;
#pragma unroll
            for (int rr = 0; rr < 2; rr++) {      // row offset 0 / +8
                int gr = row0 + rr * 8;
#pragma unroll
                for (int cc = 0; cc < 2; cc++) {
                    int gc = col0 + cc;
                    if (gc < N) {
                        float v = acc[mt][nt][rr * 2 + cc];
                        if (resid) v += resid[(size_t)gr * N + gc];
                        C[(size_t)gr * N + gc] = v;
                    }
                }
            }
        }
    }
}

// ---------------- 3. causal depthwise conv (K=4) + bias + SiLU ----------------
__global__ void conv_silu_kernel(const float* __restrict__ cw,
                                 const float* __restrict__ cb)
{
    int c = blockIdx.x * 256 + threadIdx.x;   // 0..3071
    int s = blockIdx.y;
    float acc = cb[c];
#pragma unroll
    for (int k = 0; k < K_CONV; k++) {
        int ss = s - (K_CONV - 1) + k;
        if (ss >= 0)
            acc += cw[c * K_CONV + k] * g_proj[(size_t)ss * D_PROJ + OFF_XBC + c];
    }
    g_xbc[(size_t)s * CONV_DIM + c] = siluf_(acc);
}

// ---------------- 4. dt / dA ----------------
__global__ void dt_kernel(const float* __restrict__ dt_bias,
                          const float* __restrict__ A_log)
{
    int idx = blockIdx.x * 256 + threadIdx.x;   // S*H
    int s = idx >> 5;
    int h = idx & 31;
    float x = g_proj[(size_t)s * D_PROJ + OFF_DT + h] + dt_bias[h];
    float dt = (x > 20.f) ? x : log1pf(expf(x));
    float A = -expf(A_log[h]);
    g_dt[idx] = dt;
    g_dA[idx] = expf(dt * A);
}

// ---------------- 5. sequential SSM scan (p-split x2) ----------------
// grid = (H, 2); block = 256. Block handles p in [half*32, half*32+32).
// Thread layout: p_local = w*4 + (lane&3)  (w = warp id 0..7),
//                seg = lane>>2 (0..7), n = seg*8 + i (8 state regs).
// y[p] reduced over seg lanes via shfl_xor 4/8/16.
#define CHUNK 16
__global__ void scan_kernel()
{
    int h    = blockIdx.x;
    int half = blockIdx.y;
    int g    = h >> 2;
    int pbase = half * 32;

    int tid = threadIdx.x;
    int w = tid >> 5;
    int lane = tid & 31;
    int p_local = w * 4 + (lane & 3);     // 0..31
    int seg = lane >> 2;                  // 0..7
    int nbase = seg * 8;

    __shared__ __align__(16) float sx[CHUNK][32];
    __shared__ __align__(16) float sB[CHUNK][64];
    __shared__ __align__(16) float sC[CHUNK][64];
    __shared__ float sdA[CHUNK];
    __shared__ float sdt[CHUNK];
    __shared__ float sy[CHUNK][32];

    float hs[8];
#pragma unroll
    for (int i = 0; i < 8; i++) hs[i] = 0.f;

    for (int s0 = 0; s0 < S_LEN; s0 += CHUNK) {
        // stage x (16x32)
#pragma unroll
        for (int i = 0; i < 2; i++) {
            int t  = tid + i * 256;
            int tt = t >> 5;
            int cc = t & 31;
            sx[tt][cc] = g_xbc[(size_t)(s0 + tt) * CONV_DIM + OFF_XS + h * 64 + pbase + cc];
        }
        // stage B, C (16x64 each)
#pragma unroll
        for (int i = 0; i < 4; i++) {
            int t  = tid + i * 256;
            int tt = t >> 6;
            int cc = t & 63;
            size_t base = (size_t)(s0 + tt) * CONV_DIM;
            sB[tt][cc] = g_xbc[base + OFF_B + g * 64 + cc];
            sC[tt][cc] = g_xbc[base + OFF_C + g * 64 + cc];
        }
        if (tid < CHUNK) {
            sdA[tid] = g_dA[(size_t)(s0 + tid) * H_HEADS + h];
            sdt[tid] = g_dt[(size_t)(s0 + tid) * H_HEADS + h];
        }
        __syncthreads();

#pragma unroll 4
        for (int t = 0; t < CHUNK; t++) {
            float dAv  = sdA[t];
            float coef = sdt[t] * sx[t][p_local];
            float4 b0 = *reinterpret_cast<const float4*>(&sB[t][nbase]);
            float4 b1 = *reinterpret_cast<const float4*>(&sB[t][nbase + 4]);
            float4 c0 = *reinterpret_cast<const float4*>(&sC[t][nbase]);
            float4 c1 = *reinterpret_cast<const float4*>(&sC[t][nbase + 4]);
            float y = 0.f;
            hs[0] = dAv * hs[0] + coef * b0.x;  y += hs[0] * c0.x;
            hs[1] = dAv * hs[1] + coef * b0.y;  y += hs[1] * c0.y;
            hs[2] = dAv * hs[2] + coef * b0.z;  y += hs[2] * c0.z;
            hs[3] = dAv * hs[3] + coef * b0.w;  y += hs[3] * c0.w;
            hs[4] = dAv * hs[4] + coef * b1.x;  y += hs[4] * c1.x;
            hs[5] = dAv * hs[5] + coef * b1.y;  y += hs[5] * c1.y;
            hs[6] = dAv * hs[6] + coef * b1.z;  y += hs[6] * c1.z;
            hs[7] = dAv * hs[7] + coef * b1.w;  y += hs[7] * c1.w;
            y += __shfl_xor_sync(0xffffffffu, y, 4);
            y += __shfl_xor_sync(0xffffffffu, y, 8);
            y += __shfl_xor_sync(0xffffffffu, y, 16);
            if (seg == 0) sy[t][p_local] = y;
        }
        __syncthreads();

        // coalesced writeback of y chunk (16x32)
#pragma unroll
        for (int i = 0; i < 2; i++) {
            int t  = tid + i * 256;
            int tt = t >> 5;
            int cc = t & 31;
            g_y[(size_t)(s0 + tt) * D_INNER + h * 64 + pbase + cc] = sy[tt][cc];
        }
        __syncthreads();
    }
}

// ---------------- 6. gating + grouped RMSNorm ----------------
// grid (G, S), block 256 (= GROUP_SIZE)
__global__ void gate_kernel(const float* __restrict__ Dv,
                            const float* __restrict__ gw)
{
    int s = blockIdx.y;
    int grp = blockIdx.x;
    int tid = threadIdx.x;
    int d = grp * GROUP_SIZE + tid;
    int h = d >> 6;

    float xs = g_xbc[(size_t)s * CONV_DIM + OFF_XS + d];
    float y  = g_y[(size_t)s * D_INNER + d] + Dv[h] * xs;
    float z  = g_proj[(size_t)s * D_PROJ + OFF_Z + d];
    float gv = y * siluf_(z);

    float ss = gv * gv;
    __shared__ float red[8];
#pragma unroll
    for (int o = 16; o > 0; o >>= 1) ss += __shfl_xor_sync(0xffffffffu, ss, o);
    if ((tid & 31) == 0) red[tid >> 5] = ss;
    __syncthreads();
    __shared__ float rinv;
    if (tid == 0) {
        float t = 0.f;
#pragma unroll
        for (int i = 0; i < 8; i++) t += red[i];
        rinv = rsqrtf(t / (float)GROUP_SIZE + EPS_RMS);
    }
    __syncthreads();
    g_g[(size_t)s * D_INNER + d] = gv * rinv * gw[d];
}

// ---------------- launch ----------------
extern "C" void kernel_launch(void* const* d_in, const int* in_sizes, int n_in,
                              void* d_out, int out_size)
{
    const float* hidden      = (const float*)d_in[0];
    const float* norm_w      = (const float*)d_in[1];
    const float* in_proj_w   = (const float*)d_in[2];
    const float* conv_w      = (const float*)d_in[3];
    const float* conv_b      = (const float*)d_in[4];
    const float* dt_bias     = (const float*)d_in[5];
    const float* A_log       = (const float*)d_in[6];
    const float* Dv          = (const float*)d_in[7];
    const float* gate_norm_w = (const float*)d_in[8];
    const float* out_proj_w  = (const float*)d_in[9];
    float* out = (float*)d_out;

    void *p_xn, *p_proj, *p_g;
    cudaGetSymbolAddress(&p_xn,   g_xn);
    cudaGetSymbolAddress(&p_proj, g_proj);
    cudaGetSymbolAddress(&p_g,    g_g);

    rmsnorm_kernel<<<S_LEN, 256>>>(hidden, norm_w);

    gemm_tf32_kernel<<<dim3((D_PROJ + GBN - 1) / GBN, S_LEN / GBM), 256>>>(
        (const float*)p_xn, in_proj_w, nullptr, (float*)p_proj,
        S_LEN, D_PROJ, D_MODEL);

    conv_silu_kernel<<<dim3(CONV_DIM / 256, S_LEN), 256>>>(conv_w, conv_b);

    dt_kernel<<<(S_LEN * H_HEADS) / 256, 256>>>(dt_bias, A_log);

    scan_kernel<<<dim3(H_HEADS, 2), 256>>>();

    gate_kernel<<<dim3(G_GRP, S_LEN), 256>>>(Dv, gate_norm_w);

    gemm_tf32_kernel<<<dim3(D_MODEL / GBN, S_LEN / GBM), 256>>>(
        (const float*)p_g, out_proj_w, hidden, out,
        S_LEN, D_MODEL, D_INNER);
}

// round 4
// speedup vs baseline: 1.7737x; 1.1405x over previous
#include <cuda_runtime.h>
#include <cuda_bf16.h>
#include <math.h>
#include <stdint.h>

// ---------------- problem constants ----------------
#define S_LEN   2048
#define D_MODEL 1024
#define H_HEADS 32
#define P_DIM   64
#define N_STATE 64
#define G_GRP   8
#define K_CONV  4
#define D_INNER 2048                 // H*P
#define CONV_DIM 3072                // D_INNER + 2*G*N
#define D_PROJ  5152                 // 2*D_INNER + 2*G*N + H
#define GROUP_SIZE 256               // D_INNER / G
#define EPS_RMS 1e-5f

// proj row offsets
#define OFF_Z    0
#define OFF_XBC  2048
#define OFF_DT   5120
// xbc row offsets
#define OFF_XS   0
#define OFF_B    2048
#define OFF_C    2560

// ---------------- scratch (device globals; no allocation allowed) ----------------
__device__ __align__(16) float g_xn  [S_LEN * D_MODEL];
__device__ __align__(16) float g_proj[S_LEN * D_PROJ];
__device__ __align__(16) float g_xbc [S_LEN * CONV_DIM];
__device__ __align__(16) float g_dt  [S_LEN * H_HEADS];
__device__ __align__(16) float g_dA  [S_LEN * H_HEADS];
__device__ __align__(16) float g_y   [S_LEN * D_INNER];
__device__ __align__(16) float g_g   [S_LEN * D_INNER];

__device__ __forceinline__ float sigmoidf_(float x) { return 1.0f / (1.0f + expf(-x)); }
__device__ __forceinline__ float siluf_(float x)    { return x * sigmoidf_(x); }

__device__ __forceinline__ uint32_t f2tf32(float f) {
    uint32_t u;
    asm("cvt.rna.tf32.f32 %0, %1;" : "=r"(u) : "f"(f));
    return u;
}

__device__ __forceinline__ void mma_tf32(float* c, const uint32_t* a,
                                         uint32_t b0, uint32_t b1) {
    asm("mma.sync.aligned.m16n8k8.row.col.f32.tf32.tf32.f32 "
        "{%0,%1,%2,%3}, {%4,%5,%6,%7}, {%8,%9}, {%0,%1,%2,%3};"
        : "+f"(c[0]), "+f"(c[1]), "+f"(c[2]), "+f"(c[3])
        : "r"(a[0]), "r"(a[1]), "r"(a[2]), "r"(a[3]), "r"(b0), "r"(b1));
}

// ---------------- 1. RMSNorm ----------------
__global__ void rmsnorm_kernel(const float* __restrict__ x,
                               const float* __restrict__ w)
{
    int s = blockIdx.x;
    int tid = threadIdx.x;                   // 256
    const float* row = x + (size_t)s * D_MODEL;
    float v[4];
    float ss = 0.f;
#pragma unroll
    for (int i = 0; i < 4; i++) {
        v[i] = row[tid + i * 256];
        ss += v[i] * v[i];
    }
    __shared__ float red[8];
#pragma unroll
    for (int o = 16; o > 0; o >>= 1) ss += __shfl_xor_sync(0xffffffffu, ss, o);
    if ((tid & 31) == 0) red[tid >> 5] = ss;
    __syncthreads();
    __shared__ float rinv;
    if (tid == 0) {
        float t = 0.f;
#pragma unroll
        for (int i = 0; i < 8; i++) t += red[i];
        rinv = rsqrtf(t / (float)D_MODEL + EPS_RMS);
    }
    __syncthreads();
    float r = rinv;
    float* o = g_xn + (size_t)s * D_MODEL;
#pragma unroll
    for (int i = 0; i < 4; i++) {
        int c = tid + i * 256;
        o[c] = v[i] * r * w[c];
    }
}

// ---------------- 2. tf32 tensor-core GEMM: C[M,N] = A[M,K] @ B[K,N] (+resid) ----
// BM=128, BN=128, BK=32, 256 threads (8 warps: 4 warpM x 2 warpN, warp tile 32x64)
// Split LDG(regs)/STS pipeline, double-buffered dynamic smem.
// Requires: M % 128 == 0, K % 32 == 0, N % 4 == 0, A/B 16B-aligned.
#define GBM 128
#define GBN 128
#define GBK 32
#define GPAD 136   // row stride (floats); mod 32 == 8 -> conflict-free frag LDS
#define GEMM_SMEM_BYTES (2 * 2 * GBK * GPAD * 4)   // As + Bs, 2 buffers each

__global__ __launch_bounds__(256, 1)
void gemm_tf32_kernel(const float* __restrict__ A,
                      const float* __restrict__ B,
                      const float* __restrict__ resid,  // may be null
                      float* __restrict__ C,
                      int M, int N, int K)
{
    extern __shared__ uint32_t smem_raw[];
    // As[2][GBK][GPAD] : [k][m], Bs[2][GBK][GPAD] : [k][n]
    uint32_t (*As)[GBK][GPAD] = reinterpret_cast<uint32_t(*)[GBK][GPAD]>(smem_raw);
    uint32_t (*Bs)[GBK][GPAD] = reinterpret_cast<uint32_t(*)[GBK][GPAD]>(smem_raw + 2 * GBK * GPAD);

    int tid = threadIdx.x;
    int wid = tid >> 5, lane = tid & 31;
    int warpM = wid & 3;        // m base = warpM*32
    int warpN = wid >> 2;       // n base = warpN*64
    int grp = lane >> 2, tig = lane & 3;

    int rowBase = blockIdx.y * GBM;
    int colBase = blockIdx.x * GBN;

    float acc[2][8][4];
#pragma unroll
    for (int mt = 0; mt < 2; mt++)
#pragma unroll
        for (int nt = 0; nt < 8; nt++)
#pragma unroll
            for (int r = 0; r < 4; r++) acc[mt][nt][r] = 0.f;

    int KT = K / GBK;

    // register staging: A 128x32 -> 1024 float4 (4/thread), B 32x128 -> 1024 float4 (4/thread)
    float4 ra[4], rb[4];

    auto ldg_stage = [&](int kt) {
        int k0 = kt * GBK;
#pragma unroll
        for (int i = 0; i < 4; i++) {
            int idx = tid + i * 256;        // 0..1023
            int r  = idx >> 3;              // 0..127
            int kq = idx & 7;               // float4 idx within 32-wide k row
            ra[i] = *reinterpret_cast<const float4*>(
                A + (size_t)(rowBase + r) * K + k0 + kq * 4);
        }
#pragma unroll
        for (int i = 0; i < 4; i++) {
            int idx = tid + i * 256;
            int kk = idx >> 5;              // 0..31
            int cq = idx & 31;              // 0..31
            int gc = colBase + cq * 4;
            if (gc < N) {                   // N%4==0 -> all-or-nothing
                rb[i] = *reinterpret_cast<const float4*>(
                    B + (size_t)(k0 + kk) * N + gc);
            } else {
                rb[i] = make_float4(0.f, 0.f, 0.f, 0.f);
            }
        }
    };

    auto sts_stage = [&](int buf) {
#pragma unroll
        for (int i = 0; i < 4; i++) {
            int idx = tid + i * 256;
            int r  = idx >> 3;
            int kq = idx & 7;
            As[buf][kq * 4 + 0][r] = f2tf32(ra[i].x);
            As[buf][kq * 4 + 1][r] = f2tf32(ra[i].y);
            As[buf][kq * 4 + 2][r] = f2tf32(ra[i].z);
            As[buf][kq * 4 + 3][r] = f2tf32(ra[i].w);
        }
#pragma unroll
        for (int i = 0; i < 4; i++) {
            int idx = tid + i * 256;
            int kk = idx >> 5;
            int cq = idx & 31;
            uint4 u;
            u.x = f2tf32(rb[i].x); u.y = f2tf32(rb[i].y);
            u.z = f2tf32(rb[i].z); u.w = f2tf32(rb[i].w);
            *reinterpret_cast<uint4*>(&Bs[buf][kk][cq * 4]) = u;
        }
    };

    ldg_stage(0);
    sts_stage(0);

    for (int kt = 0; kt < KT; kt++) {
        __syncthreads();
        bool more = (kt + 1 < KT);
        if (more) ldg_stage(kt + 1);        // LDGs in flight during compute
        int buf = kt & 1;
#pragma unroll
        for (int k8 = 0; k8 < 4; k8++) {
            int kb = k8 * 8;
            uint32_t a[2][4];
#pragma unroll
            for (int mt = 0; mt < 2; mt++) {
                int m = warpM * 32 + mt * 16;
                a[mt][0] = As[buf][kb + tig    ][m + grp];
                a[mt][1] = As[buf][kb + tig    ][m + grp + 8];
                a[mt][2] = As[buf][kb + tig + 4][m + grp];
                a[mt][3] = As[buf][kb + tig + 4][m + grp + 8];
            }
#pragma unroll
            for (int nt = 0; nt < 8; nt++) {
                int n = warpN * 64 + nt * 8;
                uint32_t b0 = Bs[buf][kb + tig    ][n + grp];
                uint32_t b1 = Bs[buf][kb + tig + 4][n + grp];
                mma_tf32(acc[0][nt], a[0], b0, b1);
                mma_tf32(acc[1][nt], a[1], b0, b1);
            }
        }
        if (more) sts_stage((kt + 1) & 1);
    }

    // ---- epilogue ----
#pragma unroll
    for (int mt = 0; mt < 2; mt++) {
        int row0 = rowBase + warpM * 32 + mt * 16 + grp;
#pragma unroll
        for (int nt = 0; nt < 8; nt++) {
            int col0 = colBase + warpN * 64 + nt * 8 + tig * 2;
#pragma unroll
            for (int rr = 0; rr < 2; rr++) {      // row offset 0 / +8
                int gr = row0 + rr * 8;
#pragma unroll
                for (int cc = 0; cc < 2; cc++) {
                    int gc = col0 + cc;
                    if (gc < N) {
                        float v = acc[mt][nt][rr * 2 + cc];
                        if (resid) v += resid[(size_t)gr * N + gc];
                        C[(size_t)gr * N + gc] = v;
                    }
                }
            }
        }
    }
}

// ---------------- 3. causal depthwise conv (K=4) + bias + SiLU ----------------
__global__ void conv_silu_kernel(const float* __restrict__ cw,
                                 const float* __restrict__ cb)
{
    int c = blockIdx.x * 256 + threadIdx.x;   // 0..3071
    int s = blockIdx.y;
    float acc = cb[c];
#pragma unroll
    for (int k = 0; k < K_CONV; k++) {
        int ss = s - (K_CONV - 1) + k;
        if (ss >= 0)
            acc += cw[c * K_CONV + k] * g_proj[(size_t)ss * D_PROJ + OFF_XBC + c];
    }
    g_xbc[(size_t)s * CONV_DIM + c] = siluf_(acc);
}

// ---------------- 4. dt / dA ----------------
__global__ void dt_kernel(const float* __restrict__ dt_bias,
                          const float* __restrict__ A_log)
{
    int idx = blockIdx.x * 256 + threadIdx.x;   // S*H
    int s = idx >> 5;
    int h = idx & 31;
    float x = g_proj[(size_t)s * D_PROJ + OFF_DT + h] + dt_bias[h];
    float dt = (x > 20.f) ? x : log1pf(expf(x));
    float A = -expf(A_log[h]);
    g_dt[idx] = dt;
    g_dA[idx] = expf(dt * A);
}

// ---------------- 5. sequential SSM scan (p-split x4) ----------------
// grid = (H, 4); block = 256. Block handles p in [q*16, q*16+16).
// Thread layout: p_local = w*2 + (lane&1) (w = warp 0..7),
//                seg = lane>>1 (0..15), n = seg*4 + i (4 state regs).
// y[p] reduced over the 16 seg lanes via shfl_xor 2/4/8/16.
#define CHUNK 16
__global__ void scan_kernel()
{
    int h  = blockIdx.x;
    int q  = blockIdx.y;
    int g  = h >> 2;
    int pbase = q * 16;

    int tid = threadIdx.x;
    int w = tid >> 5;
    int lane = tid & 31;
    int p_local = w * 2 + (lane & 1);     // 0..15
    int seg = lane >> 1;                  // 0..15
    int nbase = seg * 4;

    __shared__ __align__(16) float sx[CHUNK][16];
    __shared__ __align__(16) float sB[CHUNK][64];
    __shared__ __align__(16) float sC[CHUNK][64];
    __shared__ float sdA[CHUNK];
    __shared__ float sdt[CHUNK];
    __shared__ float sy[CHUNK][16];

    float hs[4];
#pragma unroll
    for (int i = 0; i < 4; i++) hs[i] = 0.f;

    for (int s0 = 0; s0 < S_LEN; s0 += CHUNK) {
        // stage x (16x16): one element per thread
        {
            int tt = tid >> 4;
            int cc = tid & 15;
            sx[tt][cc] = g_xbc[(size_t)(s0 + tt) * CONV_DIM + OFF_XS + h * 64 + pbase + cc];
        }
        // stage B, C (16x64 each)
#pragma unroll
        for (int i = 0; i < 4; i++) {
            int t  = tid + i * 256;
            int tt = t >> 6;
            int cc = t & 63;
            size_t base = (size_t)(s0 + tt) * CONV_DIM;
            sB[tt][cc] = g_xbc[base + OFF_B + g * 64 + cc];
            sC[tt][cc] = g_xbc[base + OFF_C + g * 64 + cc];
        }
        if (tid < CHUNK) {
            sdA[tid] = g_dA[(size_t)(s0 + tid) * H_HEADS + h];
            sdt[tid] = g_dt[(size_t)(s0 + tid) * H_HEADS + h];
        }
        __syncthreads();

#pragma unroll 4
        for (int t = 0; t < CHUNK; t++) {
            float dAv  = sdA[t];
            float coef = sdt[t] * sx[t][p_local];
            float4 b = *reinterpret_cast<const float4*>(&sB[t][nbase]);
            float4 c = *reinterpret_cast<const float4*>(&sC[t][nbase]);
            float y = 0.f;
            hs[0] = dAv * hs[0] + coef * b.x;  y += hs[0] * c.x;
            hs[1] = dAv * hs[1] + coef * b.y;  y += hs[1] * c.y;
            hs[2] = dAv * hs[2] + coef * b.z;  y += hs[2] * c.z;
            hs[3] = dAv * hs[3] + coef * b.w;  y += hs[3] * c.w;
            y += __shfl_xor_sync(0xffffffffu, y, 2);
            y += __shfl_xor_sync(0xffffffffu, y, 4);
            y += __shfl_xor_sync(0xffffffffu, y, 8);
            y += __shfl_xor_sync(0xffffffffu, y, 16);
            if (seg == 0) sy[t][p_local] = y;
        }
        __syncthreads();

        // coalesced writeback of y chunk (16x16)
        {
            int tt = tid >> 4;
            int cc = tid & 15;
            g_y[(size_t)(s0 + tt) * D_INNER + h * 64 + pbase + cc] = sy[tt][cc];
        }
        __syncthreads();
    }
}

// ---------------- 6. gating + grouped RMSNorm ----------------
// grid (G, S), block 256 (= GROUP_SIZE)
__global__ void gate_kernel(const float* __restrict__ Dv,
                            const float* __restrict__ gw)
{
    int s = blockIdx.y;
    int grp = blockIdx.x;
    int tid = threadIdx.x;
    int d = grp * GROUP_SIZE + tid;
    int h = d >> 6;

    float xs = g_xbc[(size_t)s * CONV_DIM + OFF_XS + d];
    float y  = g_y[(size_t)s * D_INNER + d] + Dv[h] * xs;
    float z  = g_proj[(size_t)s * D_PROJ + OFF_Z + d];
    float gv = y * siluf_(z);

    float ss = gv * gv;
    __shared__ float red[8];
#pragma unroll
    for (int o = 16; o > 0; o >>= 1) ss += __shfl_xor_sync(0xffffffffu, ss, o);
    if ((tid & 31) == 0) red[tid >> 5] = ss;
    __syncthreads();
    __shared__ float rinv;
    if (tid == 0) {
        float t = 0.f;
#pragma unroll
        for (int i = 0; i < 8; i++) t += red[i];
        rinv = rsqrtf(t / (float)GROUP_SIZE + EPS_RMS);
    }
    __syncthreads();
    g_g[(size_t)s * D_INNER + d] = gv * rinv * gw[d];
}

// ---------------- launch ----------------
extern "C" void kernel_launch(void* const* d_in, const int* in_sizes, int n_in,
                              void* d_out, int out_size)
{
    const float* hidden      = (const float*)d_in[0];
    const float* norm_w      = (const float*)d_in[1];
    const float* in_proj_w   = (const float*)d_in[2];
    const float* conv_w      = (const float*)d_in[3];
    const float* conv_b      = (const float*)d_in[4];
    const float* dt_bias     = (const float*)d_in[5];
    const float* A_log       = (const float*)d_in[6];
    const float* Dv          = (const float*)d_in[7];
    const float* gate_norm_w = (const float*)d_in[8];
    const float* out_proj_w  = (const float*)d_in[9];
    float* out = (float*)d_out;

    void *p_xn, *p_proj, *p_g;
    cudaGetSymbolAddress(&p_xn,   g_xn);
    cudaGetSymbolAddress(&p_proj, g_proj);
    cudaGetSymbolAddress(&p_g,    g_g);

    cudaFuncSetAttribute(gemm_tf32_kernel,
                         cudaFuncAttributeMaxDynamicSharedMemorySize,
                         GEMM_SMEM_BYTES);

    rmsnorm_kernel<<<S_LEN, 256>>>(hidden, norm_w);

    gemm_tf32_kernel<<<dim3((D_PROJ + GBN - 1) / GBN, S_LEN / GBM), 256,
                       GEMM_SMEM_BYTES>>>(
        (const float*)p_xn, in_proj_w, nullptr, (float*)p_proj,
        S_LEN, D_PROJ, D_MODEL);

    conv_silu_kernel<<<dim3(CONV_DIM / 256, S_LEN), 256>>>(conv_w, conv_b);

    dt_kernel<<<(S_LEN * H_HEADS) / 256, 256>>>(dt_bias, A_log);

    scan_kernel<<<dim3(H_HEADS, 4), 256>>>();

    gate_kernel<<<dim3(G_GRP, S_LEN), 256>>>(Dv, gate_norm_w);

    gemm_tf32_kernel<<<dim3(D_MODEL / GBN, S_LEN / GBM), 256,
                       GEMM_SMEM_BYTES>>>(
        (const float*)p_g, out_proj_w, hidden, out,
        S_LEN, D_MODEL, D_INNER);
}

// round 5
// speedup vs baseline: 1.9867x; 1.1201x over previous
#include <cuda_runtime.h>
#include <cuda_bf16.h>
#include <math.h>
#include <stdint.h>

// ---------------- problem constants ----------------
#define S_LEN   2048
#define D_MODEL 1024
#define H_HEADS 32
#define P_DIM   64
#define N_STATE 64
#define G_GRP   8
#define K_CONV  4
#define D_INNER 2048                 // H*P
#define CONV_DIM 3072                // D_INNER + 2*G*N
#define D_PROJ  5152                 // 2*D_INNER + 2*G*N + H
#define GROUP_SIZE 256               // D_INNER / G
#define EPS_RMS 1e-5f

// proj row offsets
#define OFF_Z    0
#define OFF_XBC  2048
#define OFF_DT   5120
// xbc row offsets
#define OFF_XS   0
#define OFF_B    2048
#define OFF_C    2560

// ---------------- scratch (device globals; no allocation allowed) ----------------
__device__ __align__(16) float g_xn  [S_LEN * D_MODEL];
__device__ __align__(16) float g_proj[S_LEN * D_PROJ];
__device__ __align__(16) float g_xbc [S_LEN * CONV_DIM];
__device__ __align__(16) float g_dt  [S_LEN * H_HEADS];
__device__ __align__(16) float g_dA  [S_LEN * H_HEADS];
__device__ __align__(16) float g_y   [S_LEN * D_INNER];
__device__ __align__(16) float g_g   [S_LEN * D_INNER];

__device__ __forceinline__ float sigmoidf_(float x) { return 1.0f / (1.0f + expf(-x)); }
__device__ __forceinline__ float siluf_(float x)    { return x * sigmoidf_(x); }

__device__ __forceinline__ uint32_t f2tf32(float f) {
    uint32_t u;
    asm("cvt.rna.tf32.f32 %0, %1;" : "=r"(u) : "f"(f));
    return u;
}

__device__ __forceinline__ void mma_tf32(float* c, const uint32_t* a,
                                         uint32_t b0, uint32_t b1) {
    asm("mma.sync.aligned.m16n8k8.row.col.f32.tf32.tf32.f32 "
        "{%0,%1,%2,%3}, {%4,%5,%6,%7}, {%8,%9}, {%0,%1,%2,%3};"
        : "+f"(c[0]), "+f"(c[1]), "+f"(c[2]), "+f"(c[3])
        : "r"(a[0]), "r"(a[1]), "r"(a[2]), "r"(a[3]), "r"(b0), "r"(b1));
}

// ---------------- 1. RMSNorm ----------------
__global__ void rmsnorm_kernel(const float* __restrict__ x,
                               const float* __restrict__ w)
{
    int s = blockIdx.x;
    int tid = threadIdx.x;                   // 256
    const float* row = x + (size_t)s * D_MODEL;
    float v[4];
    float ss = 0.f;
#pragma unroll
    for (int i = 0; i < 4; i++) {
        v[i] = row[tid + i * 256];
        ss += v[i] * v[i];
    }
    __shared__ float red[8];
#pragma unroll
    for (int o = 16; o > 0; o >>= 1) ss += __shfl_xor_sync(0xffffffffu, ss, o);
    if ((tid & 31) == 0) red[tid >> 5] = ss;
    __syncthreads();
    __shared__ float rinv;
    if (tid == 0) {
        float t = 0.f;
#pragma unroll
        for (int i = 0; i < 8; i++) t += red[i];
        rinv = rsqrtf(t / (float)D_MODEL + EPS_RMS);
    }
    __syncthreads();
    float r = rinv;
    float* o = g_xn + (size_t)s * D_MODEL;
#pragma unroll
    for (int i = 0; i < 4; i++) {
        int c = tid + i * 256;
        o[c] = v[i] * r * w[c];
    }
}

// ---------------- 2. tf32 tensor-core GEMM ------------------------------------
// C[M,N] = A[M,K] @ B[K,N] (+resid).
// BM=128, BN template (128 or 64), BK=32, 256 threads,
// 8 warps = 4 warpM x 2 warpN, warp tile 32 x (BN/2).
// A smem layout [m][k] stride 36 -> conflict-free STS.128 AND frag LDS.
// B smem layout [k][n] stride BN+8 (==8 mod 32) -> conflict-free.
#define GBM 128
#define GBK 32
#define APAD 36                      // A row stride (words)

template<int BN>
__global__ __launch_bounds__(256)
void gemm_tf32_kernel(const float* __restrict__ A,
                      const float* __restrict__ B,
                      const float* __restrict__ resid,  // may be null
                      float* __restrict__ C,
                      int M, int N, int K)
{
    constexpr int BPAD = BN + 8;
    constexpr int NT   = BN / 16;          // MMA n-tiles per warp (8 or 4)
    constexpr int NB4  = BN / 32;          // B float4 loads per thread (4 or 2)

    extern __shared__ uint32_t smem_raw[];
    uint32_t (*As)[GBM][APAD] = reinterpret_cast<uint32_t(*)[GBM][APAD]>(smem_raw);
    uint32_t (*Bs)[GBK][BPAD] = reinterpret_cast<uint32_t(*)[GBK][BPAD]>(smem_raw + 2 * GBM * APAD);

    int tid = threadIdx.x;
    int wid = tid >> 5, lane = tid & 31;
    int warpM = wid & 3;                   // m base = warpM*32
    int warpN = wid >> 2;                  // n base = warpN*(BN/2)
    int grp = lane >> 2, tig = lane & 3;

    int rowBase = blockIdx.y * GBM;
    int colBase = blockIdx.x * BN;

    float acc[2][NT][4];
#pragma unroll
    for (int mt = 0; mt < 2; mt++)
#pragma unroll
        for (int nt = 0; nt < NT; nt++)
#pragma unroll
            for (int r = 0; r < 4; r++) acc[mt][nt][r] = 0.f;

    int KT = K / GBK;

    float4 ra[4], rb[NB4];

    auto ldg_stage = [&](int kt) {
        int k0 = kt * GBK;
#pragma unroll
        for (int i = 0; i < 4; i++) {
            int idx = tid + i * 256;        // 0..1023
            int r  = idx >> 3;              // 0..127
            int kq = idx & 7;
            ra[i] = *reinterpret_cast<const float4*>(
                A + (size_t)(rowBase + r) * K + k0 + kq * 4);
        }
#pragma unroll
        for (int i = 0; i < NB4; i++) {
            int idx = tid + i * 256;
            int kk = idx / (BN / 4);
            int cq = idx % (BN / 4);
            int gc = colBase + cq * 4;
            if (gc < N) {                   // N%4==0 -> all-or-nothing
                rb[i] = *reinterpret_cast<const float4*>(
                    B + (size_t)(k0 + kk) * N + gc);
            } else {
                rb[i] = make_float4(0.f, 0.f, 0.f, 0.f);
            }
        }
    };

    auto sts_stage = [&](int buf) {
#pragma unroll
        for (int i = 0; i < 4; i++) {
            int idx = tid + i * 256;
            int r  = idx >> 3;
            int kq = idx & 7;
            uint4 u;
            u.x = f2tf32(ra[i].x); u.y = f2tf32(ra[i].y);
            u.z = f2tf32(ra[i].z); u.w = f2tf32(ra[i].w);
            *reinterpret_cast<uint4*>(&As[buf][r][kq * 4]) = u;   // [m][k]
        }
#pragma unroll
        for (int i = 0; i < NB4; i++) {
            int idx = tid + i * 256;
            int kk = idx / (BN / 4);
            int cq = idx % (BN / 4);
            uint4 u;
            u.x = f2tf32(rb[i].x); u.y = f2tf32(rb[i].y);
            u.z = f2tf32(rb[i].z); u.w = f2tf32(rb[i].w);
            *reinterpret_cast<uint4*>(&Bs[buf][kk][cq * 4]) = u;
        }
    };

    ldg_stage(0);
    sts_stage(0);

    for (int kt = 0; kt < KT; kt++) {
        __syncthreads();
        bool more = (kt + 1 < KT);
        if (more) ldg_stage(kt + 1);
        int buf = kt & 1;
#pragma unroll
        for (int k8 = 0; k8 < 4; k8++) {
            int kb = k8 * 8;
            uint32_t a[2][4];
#pragma unroll
            for (int mt = 0; mt < 2; mt++) {
                int m = warpM * 32 + mt * 16;
                a[mt][0] = As[buf][m + grp    ][kb + tig    ];
                a[mt][1] = As[buf][m + grp + 8][kb + tig    ];
                a[mt][2] = As[buf][m + grp    ][kb + tig + 4];
                a[mt][3] = As[buf][m + grp + 8][kb + tig + 4];
            }
#pragma unroll
            for (int nt = 0; nt < NT; nt++) {
                int n = warpN * (BN / 2) + nt * 8;
                uint32_t b0 = Bs[buf][kb + tig    ][n + grp];
                uint32_t b1 = Bs[buf][kb + tig + 4][n + grp];
                mma_tf32(acc[0][nt], a[0], b0, b1);
                mma_tf32(acc[1][nt], a[1], b0, b1);
            }
        }
        if (more) sts_stage((kt + 1) & 1);
    }

    // ---- epilogue ----
#pragma unroll
    for (int mt = 0; mt < 2; mt++) {
        int row0 = rowBase + warpM * 32 + mt * 16 + grp;
#pragma unroll
        for (int nt = 0; nt < NT; nt++) {
            int col0 = colBase + warpN * (BN / 2) + nt * 8 + tig * 2;
#pragma unroll
            for (int rr = 0; rr < 2; rr++) {
                int gr = row0 + rr * 8;
#pragma unroll
                for (int cc = 0; cc < 2; cc++) {
                    int gc = col0 + cc;
                    if (gc < N) {
                        float v = acc[mt][nt][rr * 2 + cc];
                        if (resid) v += resid[(size_t)gr * N + gc];
                        C[(size_t)gr * N + gc] = v;
                    }
                }
            }
        }
    }
}

#define SMEM_BYTES_BN(BN) ((2 * GBM * APAD + 2 * GBK * ((BN) + 8)) * 4)

// ---------------- 3. causal depthwise conv (K=4) + bias + SiLU ----------------
__global__ void conv_silu_kernel(const float* __restrict__ cw,
                                 const float* __restrict__ cb)
{
    int c = blockIdx.x * 256 + threadIdx.x;   // 0..3071
    int s = blockIdx.y;
    float acc = cb[c];
#pragma unroll
    for (int k = 0; k < K_CONV; k++) {
        int ss = s - (K_CONV - 1) + k;
        if (ss >= 0)
            acc += cw[c * K_CONV + k] * g_proj[(size_t)ss * D_PROJ + OFF_XBC + c];
    }
    g_xbc[(size_t)s * CONV_DIM + c] = siluf_(acc);
}

// ---------------- 4. dt / dA ----------------
__global__ void dt_kernel(const float* __restrict__ dt_bias,
                          const float* __restrict__ A_log)
{
    int idx = blockIdx.x * 256 + threadIdx.x;   // S*H
    int s = idx >> 5;
    int h = idx & 31;
    float x = g_proj[(size_t)s * D_PROJ + OFF_DT + h] + dt_bias[h];
    float dt = (x > 20.f) ? x : log1pf(expf(x));
    float A = -expf(A_log[h]);
    g_dt[idx] = dt;
    g_dA[idx] = expf(dt * A);
}

// ---------------- 5. sequential SSM scan (p-split x4) ----------------
#define CHUNK 16
__global__ void scan_kernel()
{
    int h  = blockIdx.x;
    int q  = blockIdx.y;
    int g  = h >> 2;
    int pbase = q * 16;

    int tid = threadIdx.x;
    int w = tid >> 5;
    int lane = tid & 31;
    int p_local = w * 2 + (lane & 1);     // 0..15
    int seg = lane >> 1;                  // 0..15
    int nbase = seg * 4;

    __shared__ __align__(16) float sx[CHUNK][16];
    __shared__ __align__(16) float sB[CHUNK][64];
    __shared__ __align__(16) float sC[CHUNK][64];
    __shared__ float sdA[CHUNK];
    __shared__ float sdt[CHUNK];
    __shared__ float sy[CHUNK][16];

    float hs[4];
#pragma unroll
    for (int i = 0; i < 4; i++) hs[i] = 0.f;

    for (int s0 = 0; s0 < S_LEN; s0 += CHUNK) {
        {
            int tt = tid >> 4;
            int cc = tid & 15;
            sx[tt][cc] = g_xbc[(size_t)(s0 + tt) * CONV_DIM + OFF_XS + h * 64 + pbase + cc];
        }
#pragma unroll
        for (int i = 0; i < 4; i++) {
            int t  = tid + i * 256;
            int tt = t >> 6;
            int cc = t & 63;
            size_t base = (size_t)(s0 + tt) * CONV_DIM;
            sB[tt][cc] = g_xbc[base + OFF_B + g * 64 + cc];
            sC[tt][cc] = g_xbc[base + OFF_C + g * 64 + cc];
        }
        if (tid < CHUNK) {
            sdA[tid] = g_dA[(size_t)(s0 + tid) * H_HEADS + h];
            sdt[tid] = g_dt[(size_t)(s0 + tid) * H_HEADS + h];
        }
        __syncthreads();

#pragma unroll 4
        for (int t = 0; t < CHUNK; t++) {
            float dAv  = sdA[t];
            float coef = sdt[t] * sx[t][p_local];
            float4 b = *reinterpret_cast<const float4*>(&sB[t][nbase]);
            float4 c = *reinterpret_cast<const float4*>(&sC[t][nbase]);
            float y = 0.f;
            hs[0] = dAv * hs[0] + coef * b.x;  y += hs[0] * c.x;
            hs[1] = dAv * hs[1] + coef * b.y;  y += hs[1] * c.y;
            hs[2] = dAv * hs[2] + coef * b.z;  y += hs[2] * c.z;
            hs[3] = dAv * hs[3] + coef * b.w;  y += hs[3] * c.w;
            y += __shfl_xor_sync(0xffffffffu, y, 2);
            y += __shfl_xor_sync(0xffffffffu, y, 4);
            y += __shfl_xor_sync(0xffffffffu, y, 8);
            y += __shfl_xor_sync(0xffffffffu, y, 16);
            if (seg == 0) sy[t][p_local] = y;
        }
        __syncthreads();

        {
            int tt = tid >> 4;
            int cc = tid & 15;
            g_y[(size_t)(s0 + tt) * D_INNER + h * 64 + pbase + cc] = sy[tt][cc];
        }
        __syncthreads();
    }
}

// ---------------- 6. gating + grouped RMSNorm ----------------
__global__ void gate_kernel(const float* __restrict__ Dv,
                            const float* __restrict__ gw)
{
    int s = blockIdx.y;
    int grp = blockIdx.x;
    int tid = threadIdx.x;
    int d = grp * GROUP_SIZE + tid;
    int h = d >> 6;

    float xs = g_xbc[(size_t)s * CONV_DIM + OFF_XS + d];
    float y  = g_y[(size_t)s * D_INNER + d] + Dv[h] * xs;
    float z  = g_proj[(size_t)s * D_PROJ + OFF_Z + d];
    float gv = y * siluf_(z);

    float ss = gv * gv;
    __shared__ float red[8];
#pragma unroll
    for (int o = 16; o > 0; o >>= 1) ss += __shfl_xor_sync(0xffffffffu, ss, o);
    if ((tid & 31) == 0) red[tid >> 5] = ss;
    __syncthreads();
    __shared__ float rinv;
    if (tid == 0) {
        float t = 0.f;
#pragma unroll
        for (int i = 0; i < 8; i++) t += red[i];
        rinv = rsqrtf(t / (float)GROUP_SIZE + EPS_RMS);
    }
    __syncthreads();
    g_g[(size_t)s * D_INNER + d] = gv * rinv * gw[d];
}

// ---------------- launch ----------------
extern "C" void kernel_launch(void* const* d_in, const int* in_sizes, int n_in,
                              void* d_out, int out_size)
{
    const float* hidden      = (const float*)d_in[0];
    const float* norm_w      = (const float*)d_in[1];
    const float* in_proj_w   = (const float*)d_in[2];
    const float* conv_w      = (const float*)d_in[3];
    const float* conv_b      = (const float*)d_in[4];
    const float* dt_bias     = (const float*)d_in[5];
    const float* A_log       = (const float*)d_in[6];
    const float* Dv          = (const float*)d_in[7];
    const float* gate_norm_w = (const float*)d_in[8];
    const float* out_proj_w  = (const float*)d_in[9];
    float* out = (float*)d_out;

    void *p_xn, *p_proj, *p_g;
    cudaGetSymbolAddress(&p_xn,   g_xn);
    cudaGetSymbolAddress(&p_proj, g_proj);
    cudaGetSymbolAddress(&p_g,    g_g);

    cudaFuncSetAttribute(gemm_tf32_kernel<128>,
                         cudaFuncAttributeMaxDynamicSharedMemorySize,
                         SMEM_BYTES_BN(128));
    cudaFuncSetAttribute(gemm_tf32_kernel<64>,
                         cudaFuncAttributeMaxDynamicSharedMemorySize,
                         SMEM_BYTES_BN(64));

    rmsnorm_kernel<<<S_LEN, 256>>>(hidden, norm_w);

    gemm_tf32_kernel<128><<<dim3((D_PROJ + 127) / 128, S_LEN / GBM), 256,
                            SMEM_BYTES_BN(128)>>>(
        (const float*)p_xn, in_proj_w, nullptr, (float*)p_proj,
        S_LEN, D_PROJ, D_MODEL);

    conv_silu_kernel<<<dim3(CONV_DIM / 256, S_LEN), 256>>>(conv_w, conv_b);

    dt_kernel<<<(S_LEN * H_HEADS) / 256, 256>>>(dt_bias, A_log);

    scan_kernel<<<dim3(H_HEADS, 4), 256>>>();

    gate_kernel<<<dim3(G_GRP, S_LEN), 256>>>(Dv, gate_norm_w);

    gemm_tf32_kernel<64><<<dim3(D_MODEL / 64, S_LEN / GBM), 256,
                           SMEM_BYTES_BN(64)>>>(
        (const float*)p_g, out_proj_w, hidden, out,
        S_LEN, D_MODEL, D_INNER);
}

// round 8
// speedup vs baseline: 2.3952x; 1.2056x over previous
#include <cuda_runtime.h>
#include <cuda_fp16.h>
#include <math.h>
#include <stdint.h>

// ---------------- problem constants ----------------
#define S_LEN   2048
#define D_MODEL 1024
#define H_HEADS 32
#define P_DIM   64
#define N_STATE 64
#define G_GRP   8
#define K_CONV  4
#define D_INNER 2048                 // H*P
#define CONV_DIM 3072                // D_INNER + 2*G*N
#define D_PROJ  5152                 // 2*D_INNER + 2*G*N + H
#define GROUP_SIZE 256               // D_INNER / G
#define EPS_RMS 1e-5f

// proj row offsets
#define OFF_Z    0
#define OFF_XBC  2048
#define OFF_DT   5120
// xbc row offsets
#define OFF_XS   0
#define OFF_B    2048
#define OFF_C    2560

// ---------------- scratch (device globals; no allocation allowed) ----------------
__device__ __align__(16) float g_xn  [S_LEN * D_MODEL];
__device__ __align__(16) float g_proj[S_LEN * D_PROJ];
__device__ __align__(16) float g_xbc [S_LEN * CONV_DIM];
__device__ __align__(16) float g_dt  [S_LEN * H_HEADS];
__device__ __align__(16) float g_dA  [S_LEN * H_HEADS];
__device__ __align__(16) float g_y   [S_LEN * D_INNER];
__device__ __align__(16) float g_g   [S_LEN * D_INNER];

__device__ __forceinline__ float sigmoidf_(float x) { return 1.0f / (1.0f + expf(-x)); }
__device__ __forceinline__ float siluf_(float x)    { return x * sigmoidf_(x); }

// pack two floats into f16x2 (lo in low half, hi in high half)
__device__ __forceinline__ uint32_t pack_half2(float lo, float hi) {
    uint32_t u;
    asm("cvt.rn.f16x2.f32 %0, %1, %2;" : "=r"(u) : "f"(hi), "f"(lo));
    return u;
}

// fp16 MMA m16n8k16, fp32 accumulate
__device__ __forceinline__ void mma_f16(float* c, const uint32_t* a,
                                        uint32_t b0, uint32_t b1) {
    asm("mma.sync.aligned.m16n8k16.row.col.f32.f16.f16.f32 "
        "{%0,%1,%2,%3}, {%4,%5,%6,%7}, {%8,%9}, {%0,%1,%2,%3};"
        : "+f"(c[0]), "+f"(c[1]), "+f"(c[2]), "+f"(c[3])
        : "r"(a[0]), "r"(a[1]), "r"(a[2]), "r"(a[3]), "r"(b0), "r"(b1));
}

#define LDSM_X4(r0, r1, r2, r3, addr) \
    asm volatile("ldmatrix.sync.aligned.m8n8.x4.shared.b16 {%0,%1,%2,%3}, [%4];" \
                 : "=r"(r0), "=r"(r1), "=r"(r2), "=r"(r3) : "r"(addr))
#define LDSM_X4_T(r0, r1, r2, r3, addr) \
    asm volatile("ldmatrix.sync.aligned.m8n8.x4.trans.shared.b16 {%0,%1,%2,%3}, [%4];" \
                 : "=r"(r0), "=r"(r1), "=r"(r2), "=r"(r3) : "r"(addr))

__device__ __forceinline__ uint32_t smem_u32(const void* p) {
    return (uint32_t)__cvta_generic_to_shared(p);
}

// ---------------- 1. RMSNorm ----------------
__global__ void rmsnorm_kernel(const float* __restrict__ x,
                               const float* __restrict__ w)
{
    int s = blockIdx.x;
    int tid = threadIdx.x;                   // 256
    const float* row = x + (size_t)s * D_MODEL;
    float v[4];
    float ss = 0.f;
#pragma unroll
    for (int i = 0; i < 4; i++) {
        v[i] = row[tid + i * 256];
        ss += v[i] * v[i];
    }
    __shared__ float red[8];
#pragma unroll
    for (int o = 16; o > 0; o >>= 1) ss += __shfl_xor_sync(0xffffffffu, ss, o);
    if ((tid & 31) == 0) red[tid >> 5] = ss;
    __syncthreads();
    __shared__ float rinv;
    if (tid == 0) {
        float t = 0.f;
#pragma unroll
        for (int i = 0; i < 8; i++) t += red[i];
        rinv = rsqrtf(t / (float)D_MODEL + EPS_RMS);
    }
    __syncthreads();
    float r = rinv;
    float* o = g_xn + (size_t)s * D_MODEL;
#pragma unroll
    for (int i = 0; i < 4; i++) {
        int c = tid + i * 256;
        o[c] = v[i] * r * w[c];
    }
}

// ---------------- 2. fp16 tensor-core GEMM (m16n8k16 + ldmatrix) --------------
// C[M,N] = A[M,K] @ B[K,N] (+resid), fp32 accumulate.
// BM=128, BN template (128/64), BK=32, 256 threads,
// 8 warps = 4 warpM x 2 warpN, warp tile 32 x (BN/2).
// A smem [m][k] halfs, rows padded to 80B  -> conflict-free ldmatrix (5m mod 8 distinct).
// B smem [k][n] halfs, rows padded to BN*2+16 bytes -> conflict-free ldmatrix.trans.
// Requires: M%128==0, K%32==0, N%4==0.
#define GBM 128
#define GBK 32
#define AROW 80                      // A smem row stride bytes (64 data + 16 pad)

template<int BN>
__global__ __launch_bounds__(256)
void gemm_f16_kernel(const float* __restrict__ A,
                     const float* __restrict__ B,
                     const float* __restrict__ resid,  // may be null
                     float* __restrict__ C,
                     int M, int N, int K)
{
    constexpr int BROW = BN * 2 + 16;      // B smem row stride bytes
    constexpr int NT   = BN / 16;          // MMA n-tiles per warp (8 or 4)
    constexpr int NB4  = BN / 32;          // B float4 LDGs per thread (4 or 2)

    __shared__ __align__(16) uint8_t sA[2][GBM * AROW];
    __shared__ __align__(16) uint8_t sB[2][GBK * BROW];

    int tid = threadIdx.x;
    int wid = tid >> 5, lane = tid & 31;
    int warpM = wid & 3;                   // m base = warpM*32
    int warpN = wid >> 2;                  // n base = warpN*(BN/2)
    int grp = lane >> 2, tig = lane & 3;

    int rowBase = blockIdx.y * GBM;
    int colBase = blockIdx.x * BN;

    float acc[2][NT][4];
#pragma unroll
    for (int mt = 0; mt < 2; mt++)
#pragma unroll
        for (int nt = 0; nt < NT; nt++)
#pragma unroll
            for (int r = 0; r < 4; r++) acc[mt][nt][r] = 0.f;

    int KT = K / GBK;

    float4 ra[4], rb[NB4];

    auto ldg_stage = [&](int kt) {
        int k0 = kt * GBK;
#pragma unroll
        for (int i = 0; i < 4; i++) {
            int idx = tid + i * 256;        // 0..1023
            int r  = idx >> 3;              // 0..127
            int kq = idx & 7;               // float4 within 32-float k row
            ra[i] = *reinterpret_cast<const float4*>(
                A + (size_t)(rowBase + r) * K + k0 + kq * 4);
        }
#pragma unroll
        for (int i = 0; i < NB4; i++) {
            int idx = tid + i * 256;
            int kk = idx / (BN / 4);
            int cq = idx % (BN / 4);
            int gc = colBase + cq * 4;
            if (gc < N) {                   // N%4==0 -> all-or-nothing
                rb[i] = *reinterpret_cast<const float4*>(
                    B + (size_t)(k0 + kk) * N + gc);
            } else {
                rb[i] = make_float4(0.f, 0.f, 0.f, 0.f);
            }
        }
    };

    auto sts_stage = [&](int buf) {
#pragma unroll
        for (int i = 0; i < 4; i++) {
            int idx = tid + i * 256;
            int r  = idx >> 3;
            int kq = idx & 7;
            uint2 u;
            u.x = pack_half2(ra[i].x, ra[i].y);
            u.y = pack_half2(ra[i].z, ra[i].w);
            *reinterpret_cast<uint2*>(&sA[buf][r * AROW + kq * 8]) = u;
        }
#pragma unroll
        for (int i = 0; i < NB4; i++) {
            int idx = tid + i * 256;
            int kk = idx / (BN / 4);
            int cq = idx % (BN / 4);
            uint2 u;
            u.x = pack_half2(rb[i].x, rb[i].y);
            u.y = pack_half2(rb[i].z, rb[i].w);
            *reinterpret_cast<uint2*>(&sB[buf][kk * BROW + cq * 8]) = u;
        }
    };

    // ldmatrix per-lane address components
    int a_lr = lane & 15;                  // row within 16-row tile pair
    int a_lc = lane >> 4;                  // 0/1 -> k chunk (+16B)
    int b_kof = (lane & 7) + ((lane >> 4) << 3);   // k row offset 0..15
    int b_nch = ((lane >> 3) & 1) * 8;             // n chunk 0/8

    ldg_stage(0);
    sts_stage(0);

    for (int kt = 0; kt < KT; kt++) {
        __syncthreads();
        bool more = (kt + 1 < KT);
        if (more) ldg_stage(kt + 1);
        int buf = kt & 1;
        uint32_t sa_base = smem_u32(&sA[buf][0]);
        uint32_t sb_base = smem_u32(&sB[buf][0]);
#pragma unroll
        for (int kk = 0; kk < 2; kk++) {   // two k16 steps per BK=32
            uint32_t a[2][4];
#pragma unroll
            for (int mt = 0; mt < 2; mt++) {
                int m0 = warpM * 32 + mt * 16;
                uint32_t addr = sa_base + (m0 + a_lr) * AROW + kk * 32 + a_lc * 16;
                LDSM_X4(a[mt][0], a[mt][1], a[mt][2], a[mt][3], addr);
            }
#pragma unroll
            for (int j = 0; j < NT / 2; j++) {   // pairs of n-tiles
                int n0 = warpN * (BN / 2) + j * 16;
                uint32_t addr = sb_base + (kk * 16 + b_kof) * BROW + (n0 + b_nch) * 2;
                uint32_t b0a, b0b, b1a, b1b;
                LDSM_X4_T(b0a, b0b, b1a, b1b, addr);
                mma_f16(acc[0][2 * j    ], a[0], b0a, b1a);
                mma_f16(acc[1][2 * j    ], a[1], b0a, b1a);
                mma_f16(acc[0][2 * j + 1], a[0], b0b, b1b);
                mma_f16(acc[1][2 * j + 1], a[1], b0b, b1b);
            }
        }
        if (more) sts_stage((kt + 1) & 1);
    }

    // ---- epilogue ----
#pragma unroll
    for (int mt = 0; mt < 2; mt++) {
        int row0 = rowBase + warpM * 32 + mt * 16 + grp;
#pragma unroll
        for (int nt = 0; nt < NT; nt++) {
            int col0 = colBase + warpN * (BN / 2) + nt * 8 + tig * 2;
#pragma unroll
            for (int rr = 0; rr < 2; rr++) {
                int gr = row0 + rr * 8;
#pragma unroll
                for (int cc = 0; cc < 2; cc++) {
                    int gc = col0 + cc;
                    if (gc < N) {
                        float v = acc[mt][nt][rr * 2 + cc];
                        if (resid) v += resid[(size_t)gr * N + gc];
                        C[(size_t)gr * N + gc] = v;
                    }
                }
            }
        }
    }
}

// ---------------- 3. causal depthwise conv (K=4) + bias + SiLU ----------------
__global__ void conv_silu_kernel(const float* __restrict__ cw,
                                 const float* __restrict__ cb)
{
    int c = blockIdx.x * 256 + threadIdx.x;   // 0..3071
    int s = blockIdx.y;
    float acc = cb[c];
#pragma unroll
    for (int k = 0; k < K_CONV; k++) {
        int ss = s - (K_CONV - 1) + k;
        if (ss >= 0)
            acc += cw[c * K_CONV + k] * g_proj[(size_t)ss * D_PROJ + OFF_XBC + c];
    }
    g_xbc[(size_t)s * CONV_DIM + c] = siluf_(acc);
}

// ---------------- 4. dt / dA ----------------
__global__ void dt_kernel(const float* __restrict__ dt_bias,
                          const float* __restrict__ A_log)
{
    int idx = blockIdx.x * 256 + threadIdx.x;   // S*H
    int s = idx >> 5;
    int h = idx & 31;
    float x = g_proj[(size_t)s * D_PROJ + OFF_DT + h] + dt_bias[h];
    float dt = (x > 20.f) ? x : log1pf(expf(x));
    float A = -expf(A_log[h]);
    g_dt[idx] = dt;
    g_dA[idx] = expf(dt * A);
}

// ---------------- 5. sequential SSM scan (p-split x4) ----------------
#define CHUNK 16
__global__ void scan_kernel()
{
    int h  = blockIdx.x;
    int q  = blockIdx.y;
    int g  = h >> 2;
    int pbase = q * 16;

    int tid = threadIdx.x;
    int w = tid >> 5;
    int lane = tid & 31;
    int p_local = w * 2 + (lane & 1);     // 0..15
    int seg = lane >> 1;                  // 0..15
    int nbase = seg * 4;

    __shared__ __align__(16) float sx[CHUNK][16];
    __shared__ __align__(16) float sB[CHUNK][64];
    __shared__ __align__(16) float sC[CHUNK][64];
    __shared__ float sdA[CHUNK];
    __shared__ float sdt[CHUNK];
    __shared__ float sy[CHUNK][16];

    float hs[4];
#pragma unroll
    for (int i = 0; i < 4; i++) hs[i] = 0.f;

    for (int s0 = 0; s0 < S_LEN; s0 += CHUNK) {
        {
            int tt = tid >> 4;
            int cc = tid & 15;
            sx[tt][cc] = g_xbc[(size_t)(s0 + tt) * CONV_DIM + OFF_XS + h * 64 + pbase + cc];
        }
#pragma unroll
        for (int i = 0; i < 4; i++) {
            int t  = tid + i * 256;
            int tt = t >> 6;
            int cc = t & 63;
            size_t base = (size_t)(s0 + tt) * CONV_DIM;
            sB[tt][cc] = g_xbc[base + OFF_B + g * 64 + cc];
            sC[tt][cc] = g_xbc[base + OFF_C + g * 64 + cc];
        }
        if (tid < CHUNK) {
            sdA[tid] = g_dA[(size_t)(s0 + tid) * H_HEADS + h];
            sdt[tid] = g_dt[(size_t)(s0 + tid) * H_HEADS + h];
        }
        __syncthreads();

#pragma unroll 4
        for (int t = 0; t < CHUNK; t++) {
            float dAv  = sdA[t];
            float coef = sdt[t] * sx[t][p_local];
            float4 b = *reinterpret_cast<const float4*>(&sB[t][nbase]);
            float4 c = *reinterpret_cast<const float4*>(&sC[t][nbase]);
            float y = 0.f;
            hs[0] = dAv * hs[0] + coef * b.x;  y += hs[0] * c.x;
            hs[1] = dAv * hs[1] + coef * b.y;  y += hs[1] * c.y;
            hs[2] = dAv * hs[2] + coef * b.z;  y += hs[2] * c.z;
            hs[3] = dAv * hs[3] + coef * b.w;  y += hs[3] * c.w;
            y += __shfl_xor_sync(0xffffffffu, y, 2);
            y += __shfl_xor_sync(0xffffffffu, y, 4);
            y += __shfl_xor_sync(0xffffffffu, y, 8);
            y += __shfl_xor_sync(0xffffffffu, y, 16);
            if (seg == 0) sy[t][p_local] = y;
        }
        __syncthreads();

        {
            int tt = tid >> 4;
            int cc = tid & 15;
            g_y[(size_t)(s0 + tt) * D_INNER + h * 64 + pbase + cc] = sy[tt][cc];
        }
        __syncthreads();
    }
}

// ---------------- 6. gating + grouped RMSNorm ----------------
__global__ void gate_kernel(const float* __restrict__ Dv,
                            const float* __restrict__ gw)
{
    int s = blockIdx.y;
    int grp = blockIdx.x;
    int tid = threadIdx.x;
    int d = grp * GROUP_SIZE + tid;
    int h = d >> 6;

    float xs = g_xbc[(size_t)s * CONV_DIM + OFF_XS + d];
    float y  = g_y[(size_t)s * D_INNER + d] + Dv[h] * xs;
    float z  = g_proj[(size_t)s * D_PROJ + OFF_Z + d];
    float gv = y * siluf_(z);

    float ss = gv * gv;
    __shared__ float red[8];
#pragma unroll
    for (int o = 16; o > 0; o >>= 1) ss += __shfl_xor_sync(0xffffffffu, ss, o);
    if ((tid & 31) == 0) red[tid >> 5] = ss;
    __syncthreads();
    __shared__ float rinv;
    if (tid == 0) {
        float t = 0.f;
#pragma unroll
        for (int i = 0; i < 8; i++) t += red[i];
        rinv = rsqrtf(t / (float)GROUP_SIZE + EPS_RMS);
    }
    __syncthreads();
    g_g[(size_t)s * D_INNER + d] = gv * rinv * gw[d];
}

// ---------------- launch ----------------
extern "C" void kernel_launch(void* const* d_in, const int* in_sizes, int n_in,
                              void* d_out, int out_size)
{
    const float* hidden      = (const float*)d_in[0];
    const float* norm_w      = (const float*)d_in[1];
    const float* in_proj_w   = (const float*)d_in[2];
    const float* conv_w      = (const float*)d_in[3];
    const float* conv_b      = (const float*)d_in[4];
    const float* dt_bias     = (const float*)d_in[5];
    const float* A_log       = (const float*)d_in[6];
    const float* Dv          = (const float*)d_in[7];
    const float* gate_norm_w = (const float*)d_in[8];
    const float* out_proj_w  = (const float*)d_in[9];
    float* out = (float*)d_out;

    void *p_xn, *p_proj, *p_g;
    cudaGetSymbolAddress(&p_xn,   g_xn);
    cudaGetSymbolAddress(&p_proj, g_proj);
    cudaGetSymbolAddress(&p_g,    g_g);

    rmsnorm_kernel<<<S_LEN, 256>>>(hidden, norm_w);

    gemm_f16_kernel<128><<<dim3((D_PROJ + 127) / 128, S_LEN / GBM), 256>>>(
        (const float*)p_xn, in_proj_w, nullptr, (float*)p_proj,
        S_LEN, D_PROJ, D_MODEL);

    conv_silu_kernel<<<dim3(CONV_DIM / 256, S_LEN), 256>>>(conv_w, conv_b);

    dt_kernel<<<(S_LEN * H_HEADS) / 256, 256>>>(dt_bias, A_log);

    scan_kernel<<<dim3(H_HEADS, 4), 256>>>();

    gate_kernel<<<dim3(G_GRP, S_LEN), 256>>>(Dv, gate_norm_w);

    gemm_f16_kernel<64><<<dim3(D_MODEL / 64, S_LEN / GBM), 256>>>(
        (const float*)p_g, out_proj_w, hidden, out,
        S_LEN, D_MODEL, D_INNER);
}

// round 9
// speedup vs baseline: 2.5100x; 1.0479x over previous
#include <cuda_runtime.h>
#include <cuda_fp16.h>
#include <math.h>
#include <stdint.h>

// ---------------- problem constants ----------------
#define S_LEN   2048
#define D_MODEL 1024
#define H_HEADS 32
#define P_DIM   64
#define N_STATE 64
#define G_GRP   8
#define K_CONV  4
#define D_INNER 2048                 // H*P
#define CONV_DIM 3072                // D_INNER + 2*G*N
#define D_PROJ  5152                 // 2*D_INNER + 2*G*N + H
#define GROUP_SIZE 256               // D_INNER / G
#define EPS_RMS 1e-5f

// proj row offsets
#define OFF_Z    0
#define OFF_XBC  2048
#define OFF_DT   5120
// xbc row offsets
#define OFF_XS   0
#define OFF_B    2048
#define OFF_C    2560

// ---------------- scratch (device globals; no allocation allowed) ----------------
__device__ __align__(16) __half g_xnh [S_LEN * D_MODEL];     // normed input, fp16
__device__ __align__(16) __half g_gh  [S_LEN * D_INNER];     // gated output, fp16
__device__ __align__(16) __half g_w1h [D_MODEL * D_PROJ];    // in_proj_w fp16
__device__ __align__(16) __half g_w2h [D_INNER * D_MODEL];   // out_proj_w fp16
__device__ __align__(16) float  g_proj[S_LEN * D_PROJ];
__device__ __align__(16) float  g_xbc [S_LEN * CONV_DIM];
__device__ __align__(16) float  g_dt  [S_LEN * H_HEADS];
__device__ __align__(16) float  g_dA  [S_LEN * H_HEADS];
__device__ __align__(16) float  g_y   [S_LEN * D_INNER];

__device__ __forceinline__ float sigmoidf_(float x) { return 1.0f / (1.0f + expf(-x)); }
__device__ __forceinline__ float siluf_(float x)    { return x * sigmoidf_(x); }

// pack two floats into f16x2 (lo in low half, hi in high half)
__device__ __forceinline__ uint32_t pack_half2(float lo, float hi) {
    uint32_t u;
    asm("cvt.rn.f16x2.f32 %0, %1, %2;" : "=r"(u) : "f"(hi), "f"(lo));
    return u;
}

// fp16 MMA m16n8k16, fp32 accumulate
__device__ __forceinline__ void mma_f16(float* c, const uint32_t* a,
                                        uint32_t b0, uint32_t b1) {
    asm("mma.sync.aligned.m16n8k16.row.col.f32.f16.f16.f32 "
        "{%0,%1,%2,%3}, {%4,%5,%6,%7}, {%8,%9}, {%0,%1,%2,%3};"
        : "+f"(c[0]), "+f"(c[1]), "+f"(c[2]), "+f"(c[3])
        : "r"(a[0]), "r"(a[1]), "r"(a[2]), "r"(a[3]), "r"(b0), "r"(b1));
}

#define LDSM_X4(r0, r1, r2, r3, addr) \
    asm volatile("ldmatrix.sync.aligned.m8n8.x4.shared.b16 {%0,%1,%2,%3}, [%4];" \
                 : "=r"(r0), "=r"(r1), "=r"(r2), "=r"(r3) : "r"(addr))
#define LDSM_X4_T(r0, r1, r2, r3, addr) \
    asm volatile("ldmatrix.sync.aligned.m8n8.x4.trans.shared.b16 {%0,%1,%2,%3}, [%4];" \
                 : "=r"(r0), "=r"(r1), "=r"(r2), "=r"(r3) : "r"(addr))

__device__ __forceinline__ uint32_t smem_u32(const void* p) {
    return (uint32_t)__cvta_generic_to_shared(p);
}

// cp.async 16B with zero-fill src-size
__device__ __forceinline__ void cp16(uint32_t dst, const void* src, int sz) {
    asm volatile("cp.async.cg.shared.global [%0], [%1], 16, %2;"
                 :: "r"(dst), "l"(src), "r"(sz));
}
#define CP_COMMIT() asm volatile("cp.async.commit_group;" ::: "memory")
#define CP_WAIT(n)  asm volatile("cp.async.wait_group %0;" :: "n"(n) : "memory")

// ---------------- 0. fp32 -> fp16 conversion prepass ----------------
__global__ void f32h_kernel(const float* __restrict__ src,
                            __half* __restrict__ dst, int n4)
{
    int i = blockIdx.x * 256 + threadIdx.x;
    if (i < n4) {
        float4 v = reinterpret_cast<const float4*>(src)[i];
        uint2 u;
        u.x = pack_half2(v.x, v.y);
        u.y = pack_half2(v.z, v.w);
        reinterpret_cast<uint2*>(dst)[i] = u;
    }
}

// ---------------- 1. RMSNorm (fp16 out) ----------------
__global__ void rmsnorm_kernel(const float* __restrict__ x,
                               const float* __restrict__ w)
{
    int s = blockIdx.x;
    int tid = threadIdx.x;                   // 256
    const float* row = x + (size_t)s * D_MODEL;
    float v[4];
    float ss = 0.f;
#pragma unroll
    for (int i = 0; i < 4; i++) {
        v[i] = row[tid + i * 256];
        ss += v[i] * v[i];
    }
    __shared__ float red[8];
#pragma unroll
    for (int o = 16; o > 0; o >>= 1) ss += __shfl_xor_sync(0xffffffffu, ss, o);
    if ((tid & 31) == 0) red[tid >> 5] = ss;
    __syncthreads();
    __shared__ float rinv;
    if (tid == 0) {
        float t = 0.f;
#pragma unroll
        for (int i = 0; i < 8; i++) t += red[i];
        rinv = rsqrtf(t / (float)D_MODEL + EPS_RMS);
    }
    __syncthreads();
    float r = rinv;
    __half* o = g_xnh + (size_t)s * D_MODEL;
#pragma unroll
    for (int i = 0; i < 4; i++) {
        int c = tid + i * 256;
        o[c] = __float2half(v[i] * r * w[c]);
    }
}

// ---------------- 2. fp16 GEMM with cp.async pipeline -------------------------
// C[M,N] = A[M,K] @ B[K,N] (+resid), A/B fp16 in gmem, fp32 accumulate.
// BM=128, BN template (128/64), BK=32, 256 threads, 3-stage cp.async ring,
// 8 warps = 4 warpM x 2 warpN, warp tile 32 x (BN/2).
// A smem [m][k] halfs, 80B rows; B smem [k][n] halfs, BN*2+16 B rows.
// Requires: M%128==0, K%32==0, N%8==0.
#define GBM 128
#define GBK 32
#define AROW 80
#define ASTG (GBM * AROW)            // 10240 B per A stage

template<int BN>
__global__ __launch_bounds__(256, 2)
void gemm_h_kernel(const __half* __restrict__ A,
                   const __half* __restrict__ B,
                   const float* __restrict__ resid,  // may be null
                   float* __restrict__ C,
                   int M, int N, int K)
{
    constexpr int BROW = BN * 2 + 16;
    constexpr int BSTG = GBK * BROW;
    constexpr int NT   = BN / 16;          // MMA n-tiles per warp
    constexpr int NBC  = (GBK * (BN / 8)) / 256;   // B chunks per thread (2 or 1)

    extern __shared__ __align__(16) uint8_t smem[];
    uint32_t saA = smem_u32(smem);
    uint32_t saB = saA + 3 * ASTG;

    int tid = threadIdx.x;
    int wid = tid >> 5, lane = tid & 31;
    int warpM = wid & 3;
    int warpN = wid >> 2;
    int grp = lane >> 2, tig = lane & 3;

    int rowBase = blockIdx.y * GBM;
    int colBase = blockIdx.x * BN;

    float acc[2][NT][4];
#pragma unroll
    for (int mt = 0; mt < 2; mt++)
#pragma unroll
        for (int nt = 0; nt < NT; nt++)
#pragma unroll
            for (int r = 0; r < 4; r++) acc[mt][nt][r] = 0.f;

    int KT = K / GBK;

    auto issue_stage = [&](int kt) {
        int buf = kt % 3;
        int k0 = kt * GBK;
        // A: 128 rows x 64B = 512 chunks, 2 per thread
#pragma unroll
        for (int i = 0; i < 2; i++) {
            int idx = tid + i * 256;        // 0..511
            int r  = idx >> 2;
            int kq = idx & 3;
            cp16(saA + buf * ASTG + r * AROW + kq * 16,
                 A + (size_t)(rowBase + r) * K + k0 + kq * 8, 16);
        }
        // B: 32 rows x BN/8 chunks
#pragma unroll
        for (int i = 0; i < NBC; i++) {
            int idx = tid + i * 256;
            int kk = idx / (BN / 8);
            int cq = idx % (BN / 8);
            int gc = colBase + cq * 8;
            int ok = (gc < N);              // N%8==0 -> all-or-nothing
            cp16(saB + buf * BSTG + kk * BROW + cq * 16,
                 B + (size_t)(k0 + kk) * N + (ok ? gc : 0), ok ? 16 : 0);
        }
        CP_COMMIT();
    };

    // ldmatrix per-lane address components
    int a_lr = lane & 15;
    int a_lc = lane >> 4;
    int b_kof = (lane & 7) + ((lane >> 4) << 3);
    int b_nch = ((lane >> 3) & 1) * 8;

    issue_stage(0);
    if (KT > 1) issue_stage(1);

    for (int kt = 0; kt < KT; kt++) {
        if (kt + 1 < KT) { CP_WAIT(1); } else { CP_WAIT(0); }
        __syncthreads();
        if (kt + 2 < KT) issue_stage(kt + 2);

        int buf = kt % 3;
        uint32_t sa_base = saA + buf * ASTG;
        uint32_t sb_base = saB + buf * BSTG;
#pragma unroll
        for (int kk = 0; kk < 2; kk++) {   // two k16 steps per BK=32
            uint32_t a[2][4];
#pragma unroll
            for (int mt = 0; mt < 2; mt++) {
                int m0 = warpM * 32 + mt * 16;
                uint32_t addr = sa_base + (m0 + a_lr) * AROW + kk * 32 + a_lc * 16;
                LDSM_X4(a[mt][0], a[mt][1], a[mt][2], a[mt][3], addr);
            }
#pragma unroll
            for (int j = 0; j < NT / 2; j++) {
                int n0 = warpN * (BN / 2) + j * 16;
                uint32_t addr = sb_base + (kk * 16 + b_kof) * BROW + (n0 + b_nch) * 2;
                uint32_t b0a, b0b, b1a, b1b;
                LDSM_X4_T(b0a, b0b, b1a, b1b, addr);
                mma_f16(acc[0][2 * j    ], a[0], b0a, b1a);
                mma_f16(acc[1][2 * j    ], a[1], b0a, b1a);
                mma_f16(acc[0][2 * j + 1], a[0], b0b, b1b);
                mma_f16(acc[1][2 * j + 1], a[1], b0b, b1b);
            }
        }
        __syncthreads();     // all warps done reading buf before it is refilled
    }

    // ---- epilogue ----
#pragma unroll
    for (int mt = 0; mt < 2; mt++) {
        int row0 = rowBase + warpM * 32 + mt * 16 + grp;
#pragma unroll
        for (int nt = 0; nt < NT; nt++) {
            int col0 = colBase + warpN * (BN / 2) + nt * 8 + tig * 2;
#pragma unroll
            for (int rr = 0; rr < 2; rr++) {
                int gr = row0 + rr * 8;
#pragma unroll
                for (int cc = 0; cc < 2; cc++) {
                    int gc = col0 + cc;
                    if (gc < N) {
                        float v = acc[mt][nt][rr * 2 + cc];
                        if (resid) v += resid[(size_t)gr * N + gc];
                        C[(size_t)gr * N + gc] = v;
                    }
                }
            }
        }
    }
}

#define GEMM_SMEM_BN(BN) (3 * ASTG + 3 * GBK * ((BN) * 2 + 16))

// ---------------- 3. causal depthwise conv (K=4) + bias + SiLU ----------------
__global__ void conv_silu_kernel(const float* __restrict__ cw,
                                 const float* __restrict__ cb)
{
    int c = blockIdx.x * 256 + threadIdx.x;   // 0..3071
    int s = blockIdx.y;
    float acc = cb[c];
#pragma unroll
    for (int k = 0; k < K_CONV; k++) {
        int ss = s - (K_CONV - 1) + k;
        if (ss >= 0)
            acc += cw[c * K_CONV + k] * g_proj[(size_t)ss * D_PROJ + OFF_XBC + c];
    }
    g_xbc[(size_t)s * CONV_DIM + c] = siluf_(acc);
}

// ---------------- 4. dt / dA ----------------
__global__ void dt_kernel(const float* __restrict__ dt_bias,
                          const float* __restrict__ A_log)
{
    int idx = blockIdx.x * 256 + threadIdx.x;   // S*H
    int s = idx >> 5;
    int h = idx & 31;
    float x = g_proj[(size_t)s * D_PROJ + OFF_DT + h] + dt_bias[h];
    float dt = (x > 20.f) ? x : log1pf(expf(x));
    float A = -expf(A_log[h]);
    g_dt[idx] = dt;
    g_dA[idx] = expf(dt * A);
}

// ---------------- 5. sequential SSM scan (p-split x4) ----------------
#define CHUNK 16
__global__ void scan_kernel()
{
    int h  = blockIdx.x;
    int q  = blockIdx.y;
    int g  = h >> 2;
    int pbase = q * 16;

    int tid = threadIdx.x;
    int w = tid >> 5;
    int lane = tid & 31;
    int p_local = w * 2 + (lane & 1);     // 0..15
    int seg = lane >> 1;                  // 0..15
    int nbase = seg * 4;

    __shared__ __align__(16) float sx[CHUNK][16];
    __shared__ __align__(16) float sB[CHUNK][64];
    __shared__ __align__(16) float sC[CHUNK][64];
    __shared__ float sdA[CHUNK];
    __shared__ float sdt[CHUNK];
    __shared__ float sy[CHUNK][16];

    float hs[4];
#pragma unroll
    for (int i = 0; i < 4; i++) hs[i] = 0.f;

    for (int s0 = 0; s0 < S_LEN; s0 += CHUNK) {
        {
            int tt = tid >> 4;
            int cc = tid & 15;
            sx[tt][cc] = g_xbc[(size_t)(s0 + tt) * CONV_DIM + OFF_XS + h * 64 + pbase + cc];
        }
#pragma unroll
        for (int i = 0; i < 4; i++) {
            int t  = tid + i * 256;
            int tt = t >> 6;
            int cc = t & 63;
            size_t base = (size_t)(s0 + tt) * CONV_DIM;
            sB[tt][cc] = g_xbc[base + OFF_B + g * 64 + cc];
            sC[tt][cc] = g_xbc[base + OFF_C + g * 64 + cc];
        }
        if (tid < CHUNK) {
            sdA[tid] = g_dA[(size_t)(s0 + tid) * H_HEADS + h];
            sdt[tid] = g_dt[(size_t)(s0 + tid) * H_HEADS + h];
        }
        __syncthreads();

#pragma unroll 4
        for (int t = 0; t < CHUNK; t++) {
            float dAv  = sdA[t];
            float coef = sdt[t] * sx[t][p_local];
            float4 b = *reinterpret_cast<const float4*>(&sB[t][nbase]);
            float4 c = *reinterpret_cast<const float4*>(&sC[t][nbase]);
            float y = 0.f;
            hs[0] = dAv * hs[0] + coef * b.x;  y += hs[0] * c.x;
            hs[1] = dAv * hs[1] + coef * b.y;  y += hs[1] * c.y;
            hs[2] = dAv * hs[2] + coef * b.z;  y += hs[2] * c.z;
            hs[3] = dAv * hs[3] + coef * b.w;  y += hs[3] * c.w;
            y += __shfl_xor_sync(0xffffffffu, y, 2);
            y += __shfl_xor_sync(0xffffffffu, y, 4);
            y += __shfl_xor_sync(0xffffffffu, y, 8);
            y += __shfl_xor_sync(0xffffffffu, y, 16);
            if (seg == 0) sy[t][p_local] = y;
        }
        __syncthreads();

        {
            int tt = tid >> 4;
            int cc = tid & 15;
            g_y[(size_t)(s0 + tt) * D_INNER + h * 64 + pbase + cc] = sy[tt][cc];
        }
        __syncthreads();
    }
}

// ---------------- 6. gating + grouped RMSNorm (fp16 out) ----------------
__global__ void gate_kernel(const float* __restrict__ Dv,
                            const float* __restrict__ gw)
{
    int s = blockIdx.y;
    int grp = blockIdx.x;
    int tid = threadIdx.x;
    int d = grp * GROUP_SIZE + tid;
    int h = d >> 6;

    float xs = g_xbc[(size_t)s * CONV_DIM + OFF_XS + d];
    float y  = g_y[(size_t)s * D_INNER + d] + Dv[h] * xs;
    float z  = g_proj[(size_t)s * D_PROJ + OFF_Z + d];
    float gv = y * siluf_(z);

    float ss = gv * gv;
    __shared__ float red[8];
#pragma unroll
    for (int o = 16; o > 0; o >>= 1) ss += __shfl_xor_sync(0xffffffffu, ss, o);
    if ((tid & 31) == 0) red[tid >> 5] = ss;
    __syncthreads();
    __shared__ float rinv;
    if (tid == 0) {
        float t = 0.f;
#pragma unroll
        for (int i = 0; i < 8; i++) t += red[i];
        rinv = rsqrtf(t / (float)GROUP_SIZE + EPS_RMS);
    }
    __syncthreads();
    g_gh[(size_t)s * D_INNER + d] = __float2half(gv * rinv * gw[d]);
}

// ---------------- launch ----------------
extern "C" void kernel_launch(void* const* d_in, const int* in_sizes, int n_in,
                              void* d_out, int out_size)
{
    const float* hidden      = (const float*)d_in[0];
    const float* norm_w      = (const float*)d_in[1];
    const float* in_proj_w   = (const float*)d_in[2];
    const float* conv_w      = (const float*)d_in[3];
    const float* conv_b      = (const float*)d_in[4];
    const float* dt_bias     = (const float*)d_in[5];
    const float* A_log       = (const float*)d_in[6];
    const float* Dv          = (const float*)d_in[7];
    const float* gate_norm_w = (const float*)d_in[8];
    const float* out_proj_w  = (const float*)d_in[9];
    float* out = (float*)d_out;

    void *p_xnh, *p_proj, *p_gh, *p_w1h, *p_w2h;
    cudaGetSymbolAddress(&p_xnh,  g_xnh);
    cudaGetSymbolAddress(&p_proj, g_proj);
    cudaGetSymbolAddress(&p_gh,   g_gh);
    cudaGetSymbolAddress(&p_w1h,  g_w1h);
    cudaGetSymbolAddress(&p_w2h,  g_w2h);

    cudaFuncSetAttribute(gemm_h_kernel<128>,
                         cudaFuncAttributeMaxDynamicSharedMemorySize,
                         GEMM_SMEM_BN(128));
    cudaFuncSetAttribute(gemm_h_kernel<64>,
                         cudaFuncAttributeMaxDynamicSharedMemorySize,
                         GEMM_SMEM_BN(64));

    // weight conversion prepass (fp32 -> fp16)
    {
        int n4 = (D_MODEL * D_PROJ) / 4;
        f32h_kernel<<<(n4 + 255) / 256, 256>>>(in_proj_w, (__half*)p_w1h, n4);
        n4 = (D_INNER * D_MODEL) / 4;
        f32h_kernel<<<(n4 + 255) / 256, 256>>>(out_proj_w, (__half*)p_w2h, n4);
    }

    rmsnorm_kernel<<<S_LEN, 256>>>(hidden, norm_w);

    gemm_h_kernel<128><<<dim3((D_PROJ + 127) / 128, S_LEN / GBM), 256,
                         GEMM_SMEM_BN(128)>>>(
        (const __half*)p_xnh, (const __half*)p_w1h, nullptr, (float*)p_proj,
        S_LEN, D_PROJ, D_MODEL);

    conv_silu_kernel<<<dim3(CONV_DIM / 256, S_LEN), 256>>>(conv_w, conv_b);

    dt_kernel<<<(S_LEN * H_HEADS) / 256, 256>>>(dt_bias, A_log);

    scan_kernel<<<dim3(H_HEADS, 4), 256>>>();

    gate_kernel<<<dim3(G_GRP, S_LEN), 256>>>(Dv, gate_norm_w);

    gemm_h_kernel<64><<<dim3(D_MODEL / 64, S_LEN / GBM), 256,
                        GEMM_SMEM_BN(64)>>>(
        (const __half*)p_gh, (const __half*)p_w2h, hidden, out,
        S_LEN, D_MODEL, D_INNER);
}